// round 14
// baseline (speedup 1.0000x reference)
#include <cuda_runtime.h>
#include <cuda_bf16.h>
#include <cuda_fp16.h>
#include <cstdint>

#define NH 12
#define HD 64
#define CD 768
#define LS 1024
#define BATCH 4
#define ML (BATCH*LS)
#define ATT_SCALE 0.125f
#define LOGMAX 10.0f

// Pre-split bf16 scratch (hi+lo pairs). V is fp16 (PV path runs in fp16).
__device__ __align__(16) __nv_bfloat16 g_xqh[ML*CD], g_xql[ML*CD];  // (x+q_ape)*scale
__device__ __align__(16) __nv_bfloat16 g_xkh[ML*CD], g_xkl[ML*CD];  // x+k_ape
__device__ __align__(16) __nv_bfloat16 g_xvh[ML*CD], g_xvl[ML*CD];  // x
__device__ __align__(16) __nv_bfloat16 g_wqh[CD*CD], g_wql[CD*CD];
__device__ __align__(16) __nv_bfloat16 g_wkh[CD*CD], g_wkl[CD*CD];
__device__ __align__(16) __nv_bfloat16 g_wvh[CD*CD], g_wvl[CD*CD];
__device__ __align__(16) __nv_bfloat16 g_wph[CD*CD], g_wpl[CD*CD];
__device__ __align__(16) __nv_bfloat16 g_qh[ML*CD], g_ql[ML*CD];    // [B,H,L,D]
__device__ __align__(16) __nv_bfloat16 g_kh[ML*CD], g_kl[ML*CD];
__device__ __align__(16) __half       g_vh[ML*CD], g_vl[ML*CD];     // fp16 hi/lo
__device__ __align__(16) __nv_bfloat16 g_oh[ML*CD], g_ol[ML*CD];    // [B,L,C]

// ---------------- helpers ----------------
__device__ __forceinline__ uint32_t sptr(const void* p) {
    return (uint32_t)__cvta_generic_to_shared(p);
}
__device__ __forceinline__ void bsplit(float x, float y, uint32_t& hp, uint32_t& lp) {
    __nv_bfloat16 hx = __float2bfloat16_rn(x);
    __nv_bfloat16 hy = __float2bfloat16_rn(y);
    float rx = x - __bfloat162float(hx);
    float ry = y - __bfloat162float(hy);
    __nv_bfloat16 lx = __float2bfloat16_rn(rx);
    __nv_bfloat16 ly = __float2bfloat16_rn(ry);
    hp = (uint32_t)__bfloat16_as_ushort(hx) | ((uint32_t)__bfloat16_as_ushort(hy) << 16);
    lp = (uint32_t)__bfloat16_as_ushort(lx) | ((uint32_t)__bfloat16_as_ushort(ly) << 16);
}
__device__ __forceinline__ void hsplit(float x, float y, uint32_t& hp, uint32_t& lp) {
    __half hx = __float2half_rn(x);
    __half hy = __float2half_rn(y);
    float rx = x - __half2float(hx);
    float ry = y - __half2float(hy);
    __half lx = __float2half_rn(rx);
    __half ly = __float2half_rn(ry);
    hp = (uint32_t)__half_as_ushort(hx) | ((uint32_t)__half_as_ushort(hy) << 16);
    lp = (uint32_t)__half_as_ushort(lx) | ((uint32_t)__half_as_ushort(ly) << 16);
}
__device__ __forceinline__ uint32_t packh2(float lo, float hi) {
    uint32_t r;
    asm("cvt.rn.f16x2.f32 %0, %1, %2;" : "=r"(r) : "f"(hi), "f"(lo));
    return r;
}
__device__ __forceinline__ void ldsm4(uint32_t* r, uint32_t a) {
    asm volatile("ldmatrix.sync.aligned.m8n8.x4.shared.b16 {%0,%1,%2,%3},[%4];\n"
                 : "=r"(r[0]), "=r"(r[1]), "=r"(r[2]), "=r"(r[3]) : "r"(a));
}
__device__ __forceinline__ void ldsm4t(uint32_t* r, uint32_t a) {
    asm volatile("ldmatrix.sync.aligned.m8n8.x4.trans.shared.b16 {%0,%1,%2,%3},[%4];\n"
                 : "=r"(r[0]), "=r"(r[1]), "=r"(r[2]), "=r"(r[3]) : "r"(a));
}
__device__ __forceinline__ void mma_bf16(float* c, const uint32_t* a, uint32_t b0, uint32_t b1) {
    asm volatile(
        "mma.sync.aligned.m16n8k16.row.col.f32.bf16.bf16.f32 "
        "{%0,%1,%2,%3},{%4,%5,%6,%7},{%8,%9},{%0,%1,%2,%3};\n"
        : "+f"(c[0]), "+f"(c[1]), "+f"(c[2]), "+f"(c[3])
        : "r"(a[0]), "r"(a[1]), "r"(a[2]), "r"(a[3]), "r"(b0), "r"(b1));
}
__device__ __forceinline__ void mma_f16(float* c, const uint32_t* a, uint32_t b0, uint32_t b1) {
    asm volatile(
        "mma.sync.aligned.m16n8k16.row.col.f32.f16.f16.f32 "
        "{%0,%1,%2,%3},{%4,%5,%6,%7},{%8,%9},{%0,%1,%2,%3};\n"
        : "+f"(c[0]), "+f"(c[1]), "+f"(c[2]), "+f"(c[3])
        : "r"(a[0]), "r"(a[1]), "r"(a[2]), "r"(a[3]), "r"(b0), "r"(b1));
}
__device__ __forceinline__ void cpa16(uint32_t dst, const void* src) {
    asm volatile("cp.async.cg.shared.global [%0], [%1], 16;\n" :: "r"(dst), "l"(src));
}
__device__ __forceinline__ void cp_commit() { asm volatile("cp.async.commit_group;\n"); }
template<int N> __device__ __forceinline__ void cp_wait() {
    asm volatile("cp.async.wait_group %0;\n" :: "n"(N));
}

// ---------------------------------------------------------------------------
// Prep kernels
// ---------------------------------------------------------------------------
__global__ __launch_bounds__(256) void prep_x(
    const float* __restrict__ x,
    const float* __restrict__ qape,
    const float* __restrict__ kape)
{
    const int idx = (blockIdx.x * 256 + threadIdx.x) * 4;
    const int m = idx / CD;
    const int c = idx - m * CD;
    const int l = m & (LS - 1);

    float4 xv = *(const float4*)(x + idx);
    float4 qa = *(const float4*)(qape + (size_t)l * CD + c);
    float4 ka = *(const float4*)(kape + (size_t)l * CD + c);

    uint32_t h0, l0, h1, l1;
    bsplit((xv.x + qa.x) * ATT_SCALE, (xv.y + qa.y) * ATT_SCALE, h0, l0);
    bsplit((xv.z + qa.z) * ATT_SCALE, (xv.w + qa.w) * ATT_SCALE, h1, l1);
    *(uint2*)(g_xqh + idx) = make_uint2(h0, h1);
    *(uint2*)(g_xql + idx) = make_uint2(l0, l1);

    bsplit(xv.x + ka.x, xv.y + ka.y, h0, l0);
    bsplit(xv.z + ka.z, xv.w + ka.w, h1, l1);
    *(uint2*)(g_xkh + idx) = make_uint2(h0, h1);
    *(uint2*)(g_xkl + idx) = make_uint2(l0, l1);

    bsplit(xv.x, xv.y, h0, l0);
    bsplit(xv.z, xv.w, h1, l1);
    *(uint2*)(g_xvh + idx) = make_uint2(h0, h1);
    *(uint2*)(g_xvl + idx) = make_uint2(l0, l1);
}

__global__ __launch_bounds__(256) void prep_w(
    const float* __restrict__ Wq, const float* __restrict__ Wk,
    const float* __restrict__ Wv, const float* __restrict__ Wp)
{
    const int mat = blockIdx.y;
    const float* W = (mat == 0) ? Wq : (mat == 1) ? Wk : (mat == 2) ? Wv : Wp;
    __nv_bfloat16* wh = (mat == 0) ? g_wqh : (mat == 1) ? g_wkh : (mat == 2) ? g_wvh : g_wph;
    __nv_bfloat16* wl = (mat == 0) ? g_wql : (mat == 1) ? g_wkl : (mat == 2) ? g_wvl : g_wpl;

    const int idx = (blockIdx.x * 256 + threadIdx.x) * 4;
    float4 v = *(const float4*)(W + idx);
    uint32_t h0, l0, h1, l1;
    bsplit(v.x, v.y, h0, l0);
    bsplit(v.z, v.w, h1, l1);
    *(uint2*)(wh + idx) = make_uint2(h0, h1);
    *(uint2*)(wl + idx) = make_uint2(l0, l1);
}

// ---------------------------------------------------------------------------
// GEMM: 4-stage cp.async ring, block 128x128, BK=16, 256 thr, warp 64x32.
// ---------------------------------------------------------------------------
#define AST 24
#define GS (128*AST)
#define GIDX(st,row,col) (((st)*128+(row))*AST+(col))
#define GEMM_SMEM (4*4*GS*2)

__global__ __launch_bounds__(256, 2) void qkv_gemm()
{
    extern __shared__ __nv_bfloat16 dsm[];
    __nv_bfloat16* Ah = dsm;
    __nv_bfloat16* Al = dsm + 4*GS;
    __nv_bfloat16* Bh = dsm + 8*GS;
    __nv_bfloat16* Bl = dsm + 12*GS;

    const int which = blockIdx.z;
    const __nv_bfloat16* pAh = (which == 0) ? g_xqh : (which == 1) ? g_xkh : g_xvh;
    const __nv_bfloat16* pAl = (which == 0) ? g_xql : (which == 1) ? g_xkl : g_xvl;
    const __nv_bfloat16* pBh = (which == 0) ? g_wqh : (which == 1) ? g_wkh : g_wvh;
    const __nv_bfloat16* pBl = (which == 0) ? g_wql : (which == 1) ? g_wkl : g_wvl;
    __nv_bfloat16* outh = (which == 0) ? g_qh : (which == 1) ? g_kh : (__nv_bfloat16*)g_vh;
    __nv_bfloat16* outl = (which == 0) ? g_ql : (which == 1) ? g_kl : (__nv_bfloat16*)g_vl;

    const int tid  = threadIdx.x;
    const int lane = tid & 31;
    const int warp = tid >> 5;
    const int gid  = lane >> 2;
    const int tig  = lane & 3;
    const int wm   = warp >> 2;
    const int wn   = warp & 3;

    const int m0 = blockIdx.y * 128;
    const int n0 = blockIdx.x * 128;
    const int lr = tid >> 1;
    const int lc = (tid & 1) << 3;

    const __nv_bfloat16* ah = pAh + (size_t)(m0 + lr) * CD + lc;
    const __nv_bfloat16* al = pAl + (size_t)(m0 + lr) * CD + lc;
    const __nv_bfloat16* bh = pBh + (size_t)(n0 + lr) * CD + lc;
    const __nv_bfloat16* bl = pBl + (size_t)(n0 + lr) * CD + lc;

    float c[4][4][4];
#pragma unroll
    for (int i = 0; i < 4; i++)
#pragma unroll
        for (int j = 0; j < 4; j++)
#pragma unroll
            for (int v = 0; v < 4; v++) c[i][j][v] = 0.f;

#pragma unroll
    for (int p = 0; p < 3; p++) {
        const int k0 = p * 16;
        cpa16(sptr(&Ah[GIDX(p, lr, lc)]), ah + k0);
        cpa16(sptr(&Al[GIDX(p, lr, lc)]), al + k0);
        cpa16(sptr(&Bh[GIDX(p, lr, lc)]), bh + k0);
        cpa16(sptr(&Bl[GIDX(p, lr, lc)]), bl + k0);
        cp_commit();
    }

    const int arow_s = wm * 64 + (lane & 15);
    const int acol_s = (lane >> 4) * 8;
    const int brow_s = wn * 32 + ((lane >> 4) & 1) * 8 + (lane & 7);
    const int bcol_s = ((lane >> 3) & 1) * 8;

    const int NIT = CD / 16;
    for (int it = 0; it < NIT; ++it) {
        const int st = it & 3;
        if (it < NIT - 2)       cp_wait<2>();
        else if (it == NIT - 2) cp_wait<1>();
        else                    cp_wait<0>();
        __syncthreads();

        if (it + 3 < NIT) {
            const int s2 = (it + 3) & 3;
            const int k0 = (it + 3) * 16;
            cpa16(sptr(&Ah[GIDX(s2, lr, lc)]), ah + k0);
            cpa16(sptr(&Al[GIDX(s2, lr, lc)]), al + k0);
            cpa16(sptr(&Bh[GIDX(s2, lr, lc)]), bh + k0);
            cpa16(sptr(&Bl[GIDX(s2, lr, lc)]), bl + k0);
            cp_commit();
        }

        uint32_t fah[4][4], fal[4][4], fbh[2][4], fbl[2][4];
#pragma unroll
        for (int ma = 0; ma < 4; ma++) {
            ldsm4(fah[ma], sptr(&Ah[GIDX(st, arow_s + ma * 16, acol_s)]));
            ldsm4(fal[ma], sptr(&Al[GIDX(st, arow_s + ma * 16, acol_s)]));
        }
#pragma unroll
        for (int np = 0; np < 2; np++) {
            ldsm4(fbh[np], sptr(&Bh[GIDX(st, brow_s + np * 16, bcol_s)]));
            ldsm4(fbl[np], sptr(&Bl[GIDX(st, brow_s + np * 16, bcol_s)]));
        }
#pragma unroll
        for (int ma = 0; ma < 4; ma++)
#pragma unroll
            for (int nb = 0; nb < 4; nb++) {
                const int np = nb >> 1, sel = (nb & 1) * 2;
                mma_bf16(c[ma][nb], fah[ma], fbh[np][sel], fbh[np][sel + 1]);
                mma_bf16(c[ma][nb], fah[ma], fbl[np][sel], fbl[np][sel + 1]);
                mma_bf16(c[ma][nb], fal[ma], fbh[np][sel], fbh[np][sel + 1]);
            }
    }

    // epilogue -> [B,H,L,D]; Q/K bf16 hi/lo, V fp16 hi/lo
#pragma unroll
    for (int ma = 0; ma < 4; ma++) {
        int row0 = m0 + wm * 64 + ma * 16 + gid;
        int row1 = row0 + 8;
        int b0i = row0 >> 10, l0 = row0 & (LS - 1);
        int b1i = row1 >> 10, l1 = row1 & (LS - 1);
#pragma unroll
        for (int nb = 0; nb < 4; nb++) {
            int n = n0 + wn * 32 + nb * 8 + 2 * tig;
            int h = n >> 6, d = n & 63;
            size_t o0 = ((size_t)((b0i * NH + h) * LS + l0)) * HD + d;
            size_t o1 = ((size_t)((b1i * NH + h) * LS + l1)) * HD + d;
            uint32_t hp, lp;
            if (which == 2) hsplit(c[ma][nb][0], c[ma][nb][1], hp, lp);
            else            bsplit(c[ma][nb][0], c[ma][nb][1], hp, lp);
            *(uint32_t*)(outh + o0) = hp;
            *(uint32_t*)(outl + o0) = lp;
            if (which == 2) hsplit(c[ma][nb][2], c[ma][nb][3], hp, lp);
            else            bsplit(c[ma][nb][2], c[ma][nb][3], hp, lp);
            *(uint32_t*)(outh + o1) = hp;
            *(uint32_t*)(outl + o1) = lp;
        }
    }
}

// ---------------------------------------------------------------------------
// Attention: fixed-max softmax, software-pipelined: S(i+1) issued before
// softmax(i)/PV(i) each iteration; 3-stage cp.async KV ring; Q persistent smem.
// ---------------------------------------------------------------------------
#define KST 72
// Sb: [3][4][32][KST] bf16 = 55296 B ; Qh/Ql: [64][KST] bf16 = 9216 B each
#define ATTN_SMEM (55296 + 2*9216)
#define SIDX3(st,arr,row,col) ((((st)*4+(arr))*32+(row))*KST+(col))

__global__ __launch_bounds__(128, 3) void attn_kernel(const float* __restrict__ pos)
{
    extern __shared__ char asmem[];
    __nv_bfloat16* Sb = (__nv_bfloat16*)asmem;
    __nv_bfloat16* Qh = (__nv_bfloat16*)(asmem + 55296);
    __nv_bfloat16* Ql = Qh + 64 * KST;

    const int tid  = threadIdx.x;
    const int lane = tid & 31;
    const int warp = tid >> 5;
    const int gid  = lane >> 2;
    const int tig  = lane & 3;

    const int bh = blockIdx.y;
    const int b  = bh / NH;
    const int h  = bh - b * NH;
    const int q0 = blockIdx.x * 64;

    const size_t base = (size_t)bh * LS * HD;

    // ---- prologue: Q (group), KV(0) (group), KV(1) (group) ----
    {
        const __nv_bfloat16* src = ((warp & 2) ? g_ql : g_qh) +
            base + (size_t)(q0 + (warp & 1) * 32 + lane) * HD;
        __nv_bfloat16* dst = ((warp & 2) ? Ql : Qh) + ((warp & 1) * 32 + lane) * KST;
        uint32_t d0 = sptr(dst);
#pragma unroll
        for (int cidx = 0; cidx < 8; cidx++) cpa16(d0 + cidx * 16, src + cidx * 8);
    }
    cp_commit();

    const __nv_bfloat16* kvsrc =
        ((warp == 0) ? g_kh : (warp == 1) ? g_kl :
         (warp == 2) ? (const __nv_bfloat16*)g_vh : (const __nv_bfloat16*)g_vl) + base;

#define LOAD_KV(J, ST) do { \
    const __nv_bfloat16* src_ = kvsrc + (size_t)((J) * 32 + lane) * HD; \
    uint32_t d0_ = sptr(&Sb[SIDX3((ST), warp, lane, 0)]); \
    _Pragma("unroll") for (int c_ = 0; c_ < 8; c_++) cpa16(d0_ + c_ * 16, src_ + c_ * 8); \
    cp_commit(); } while (0)

    LOAD_KV(0, 0);
    LOAD_KV(1, 1);
    cp_wait<1>();      // Q + KV(0) done; KV(1) in flight
    __syncthreads();

    const int r = warp * 16 + gid;
    const float* pb0 = pos + ((size_t)(h * LS + q0 + r))     * LS + 2 * tig;
    const float* pb1 = pos + ((size_t)(h * LS + q0 + r + 8)) * LS + 2 * tig;

    const int qrow = warp * 16 + (lane & 15);
    const int qc   = (lane >> 4) * 8;
    const int krow_s = ((lane >> 4) & 1) * 8 + (lane & 7);
    const int kcol_s = ((lane >> 3) & 1) * 8;
    const int vrow_s = ((lane >> 3) & 1) * 8 + (lane & 7);
    const int vcol_s = ((lane >> 4) & 1) * 8;

    float o[8][4];
#pragma unroll
    for (int nd = 0; nd < 8; nd++)
#pragma unroll
        for (int v = 0; v < 4; v++) o[nd][v] = 0.f;
    float li[2] = {0.f, 0.f};
    float sA[4][4], sB[4][4];
    float2 pv0[4], pv1[4];

#define COMPUTE_S(ST, SD) do { \
    _Pragma("unroll") for (int nb_ = 0; nb_ < 4; nb_++) { \
        SD[nb_][0] = 0.f; SD[nb_][1] = 0.f; SD[nb_][2] = 0.f; SD[nb_][3] = 0.f; } \
    _Pragma("unroll") for (int kc_ = 0; kc_ < 4; kc_++) { \
        uint32_t qh_[4], ql_[4]; \
        ldsm4(qh_, sptr(Qh + qrow * KST + kc_ * 16 + qc)); \
        ldsm4(ql_, sptr(Ql + qrow * KST + kc_ * 16 + qc)); \
        _Pragma("unroll") for (int np_ = 0; np_ < 2; np_++) { \
            uint32_t kh_[4], kl_[4]; \
            ldsm4(kh_, sptr(&Sb[SIDX3((ST), 0, np_ * 16 + krow_s, kc_ * 16 + kcol_s)])); \
            ldsm4(kl_, sptr(&Sb[SIDX3((ST), 1, np_ * 16 + krow_s, kc_ * 16 + kcol_s)])); \
            mma_bf16(SD[2*np_],   qh_, kh_[0], kh_[1]); \
            mma_bf16(SD[2*np_],   qh_, kl_[0], kl_[1]); \
            mma_bf16(SD[2*np_],   ql_, kh_[0], kh_[1]); \
            mma_bf16(SD[2*np_+1], qh_, kh_[2], kh_[3]); \
            mma_bf16(SD[2*np_+1], qh_, kl_[2], kl_[3]); \
            mma_bf16(SD[2*np_+1], ql_, kh_[2], kh_[3]); \
        } } } while (0)

    const int NJ = LS / 32;   // 32

    // S(0) -> sA
    COMPUTE_S(0, sA);

#define BODY(I, SCUR, SNEXT) do { \
    const int stc_ = (I) % 3; \
    const int stn_ = ((I) + 1) % 3; \
    if ((I) + 1 < NJ) { \
        if ((I) + 2 < NJ) { LOAD_KV((I) + 2, ((I) + 2) % 3); cp_wait<1>(); } \
        else              { cp_wait<0>(); } \
        __syncthreads(); \
    } \
    _Pragma("unroll") for (int nb_ = 0; nb_ < 4; nb_++) { \
        pv0[nb_] = *(const float2*)(pb0 + (I) * 32 + nb_ * 8); \
        pv1[nb_] = *(const float2*)(pb1 + (I) * 32 + nb_ * 8); } \
    if ((I) + 1 < NJ) COMPUTE_S(stn_, SNEXT); \
    _Pragma("unroll") for (int nb_ = 0; nb_ < 4; nb_++) { \
        float e0_ = __expf(SCUR[nb_][0] + pv0[nb_].x - LOGMAX); \
        float e1_ = __expf(SCUR[nb_][1] + pv0[nb_].y - LOGMAX); \
        float e2_ = __expf(SCUR[nb_][2] + pv1[nb_].x - LOGMAX); \
        float e3_ = __expf(SCUR[nb_][3] + pv1[nb_].y - LOGMAX); \
        SCUR[nb_][0] = e0_; SCUR[nb_][1] = e1_; \
        SCUR[nb_][2] = e2_; SCUR[nb_][3] = e3_; \
        li[0] += e0_ + e1_; li[1] += e2_ + e3_; } \
    { uint32_t pf_[2][4]; \
      _Pragma("unroll") for (int kc_ = 0; kc_ < 2; kc_++) { \
          pf_[kc_][0] = packh2(SCUR[2*kc_][0],   SCUR[2*kc_][1]); \
          pf_[kc_][1] = packh2(SCUR[2*kc_][2],   SCUR[2*kc_][3]); \
          pf_[kc_][2] = packh2(SCUR[2*kc_+1][0], SCUR[2*kc_+1][1]); \
          pf_[kc_][3] = packh2(SCUR[2*kc_+1][2], SCUR[2*kc_+1][3]); } \
      _Pragma("unroll") for (int kc_ = 0; kc_ < 2; kc_++) \
          _Pragma("unroll") for (int np_ = 0; np_ < 4; np_++) { \
              uint32_t vh_[4], vl_[4]; \
              ldsm4t(vh_, sptr(&Sb[SIDX3(stc_, 2, kc_ * 16 + vrow_s, np_ * 16 + vcol_s)])); \
              ldsm4t(vl_, sptr(&Sb[SIDX3(stc_, 3, kc_ * 16 + vrow_s, np_ * 16 + vcol_s)])); \
              mma_f16(o[2*np_],   pf_[kc_], vh_[0], vh_[1]); \
              mma_f16(o[2*np_],   pf_[kc_], vl_[0], vl_[1]); \
              mma_f16(o[2*np_+1], pf_[kc_], vh_[2], vh_[3]); \
              mma_f16(o[2*np_+1], pf_[kc_], vl_[2], vl_[3]); } } \
    if ((I) + 1 < NJ) __syncthreads(); \
} while (0)

    for (int ii = 0; ii < NJ; ii += 2) {
        BODY(ii,     sA, sB);
        BODY(ii + 1, sB, sA);
    }

    // ---- final li reduction + epilogue ----
#pragma unroll
    for (int rp = 0; rp < 2; rp++) {
        li[rp] += __shfl_xor_sync(0xffffffffu, li[rp], 1);
        li[rp] += __shfl_xor_sync(0xffffffffu, li[rp], 2);
    }
    float inv0 = 1.0f / li[0];
    float inv1 = 1.0f / li[1];
#pragma unroll
    for (int nd = 0; nd < 8; nd++) {
        int d = nd * 8 + 2 * tig;
        size_t o0 = ((size_t)(b * LS + q0 + r)) * CD + h * HD + d;
        size_t o1 = ((size_t)(b * LS + q0 + r + 8)) * CD + h * HD + d;
        uint32_t hp, lp;
        bsplit(o[nd][0] * inv0, o[nd][1] * inv0, hp, lp);
        *(uint32_t*)(g_oh + o0) = hp;
        *(uint32_t*)(g_ol + o0) = lp;
        bsplit(o[nd][2] * inv1, o[nd][3] * inv1, hp, lp);
        *(uint32_t*)(g_oh + o1) = hp;
        *(uint32_t*)(g_ol + o1) = lp;
    }
#undef BODY
#undef COMPUTE_S
#undef LOAD_KV
}

// ---------------------------------------------------------------------------
// Output projection: 4-stage ring.
// ---------------------------------------------------------------------------
__global__ __launch_bounds__(256, 2) void proj_gemm(
    const float* __restrict__ bp,
    float* __restrict__ out)
{
    extern __shared__ __nv_bfloat16 dsm[];
    __nv_bfloat16* Ah = dsm;
    __nv_bfloat16* Al = dsm + 4*GS;
    __nv_bfloat16* Bh = dsm + 8*GS;
    __nv_bfloat16* Bl = dsm + 12*GS;

    const int tid  = threadIdx.x;
    const int lane = tid & 31;
    const int warp = tid >> 5;
    const int gid  = lane >> 2;
    const int tig  = lane & 3;
    const int wm   = warp >> 2;
    const int wn   = warp & 3;

    const int m0 = blockIdx.y * 128;
    const int n0 = blockIdx.x * 128;
    const int lr = tid >> 1;
    const int lc = (tid & 1) << 3;

    const __nv_bfloat16* ah = g_oh  + (size_t)(m0 + lr) * CD + lc;
    const __nv_bfloat16* al = g_ol  + (size_t)(m0 + lr) * CD + lc;
    const __nv_bfloat16* bh = g_wph + (size_t)(n0 + lr) * CD + lc;
    const __nv_bfloat16* bl = g_wpl + (size_t)(n0 + lr) * CD + lc;

    float c[4][4][4];
#pragma unroll
    for (int i = 0; i < 4; i++)
#pragma unroll
        for (int j = 0; j < 4; j++)
#pragma unroll
            for (int v = 0; v < 4; v++) c[i][j][v] = 0.f;

#pragma unroll
    for (int p = 0; p < 3; p++) {
        const int k0 = p * 16;
        cpa16(sptr(&Ah[GIDX(p, lr, lc)]), ah + k0);
        cpa16(sptr(&Al[GIDX(p, lr, lc)]), al + k0);
        cpa16(sptr(&Bh[GIDX(p, lr, lc)]), bh + k0);
        cpa16(sptr(&Bl[GIDX(p, lr, lc)]), bl + k0);
        cp_commit();
    }

    const int arow_s = wm * 64 + (lane & 15);
    const int acol_s = (lane >> 4) * 8;
    const int brow_s = wn * 32 + ((lane >> 4) & 1) * 8 + (lane & 7);
    const int bcol_s = ((lane >> 3) & 1) * 8;

    const int NIT = CD / 16;
    for (int it = 0; it < NIT; ++it) {
        const int st = it & 3;
        if (it < NIT - 2)       cp_wait<2>();
        else if (it == NIT - 2) cp_wait<1>();
        else                    cp_wait<0>();
        __syncthreads();

        if (it + 3 < NIT) {
            const int s2 = (it + 3) & 3;
            const int k0 = (it + 3) * 16;
            cpa16(sptr(&Ah[GIDX(s2, lr, lc)]), ah + k0);
            cpa16(sptr(&Al[GIDX(s2, lr, lc)]), al + k0);
            cpa16(sptr(&Bh[GIDX(s2, lr, lc)]), bh + k0);
            cpa16(sptr(&Bl[GIDX(s2, lr, lc)]), bl + k0);
            cp_commit();
        }

        uint32_t fah[4][4], fal[4][4], fbh[2][4], fbl[2][4];
#pragma unroll
        for (int ma = 0; ma < 4; ma++) {
            ldsm4(fah[ma], sptr(&Ah[GIDX(st, arow_s + ma * 16, acol_s)]));
            ldsm4(fal[ma], sptr(&Al[GIDX(st, arow_s + ma * 16, acol_s)]));
        }
#pragma unroll
        for (int np = 0; np < 2; np++) {
            ldsm4(fbh[np], sptr(&Bh[GIDX(st, brow_s + np * 16, bcol_s)]));
            ldsm4(fbl[np], sptr(&Bl[GIDX(st, brow_s + np * 16, bcol_s)]));
        }
#pragma unroll
        for (int ma = 0; ma < 4; ma++)
#pragma unroll
            for (int nb = 0; nb < 4; nb++) {
                const int np = nb >> 1, sel = (nb & 1) * 2;
                mma_bf16(c[ma][nb], fah[ma], fbh[np][sel], fbh[np][sel + 1]);
                mma_bf16(c[ma][nb], fah[ma], fbl[np][sel], fbl[np][sel + 1]);
                mma_bf16(c[ma][nb], fal[ma], fbh[np][sel], fbh[np][sel + 1]);
            }
    }

#pragma unroll
    for (int ma = 0; ma < 4; ma++) {
        int row0 = m0 + wm * 64 + ma * 16 + gid;
        int row1 = row0 + 8;
#pragma unroll
        for (int nb = 0; nb < 4; nb++) {
            int n = n0 + wn * 32 + nb * 8 + 2 * tig;
            float2 bias = *(const float2*)(bp + n);
            *(float2*)(out + (size_t)row0 * CD + n) =
                make_float2(c[ma][nb][0] + bias.x, c[ma][nb][1] + bias.y);
            *(float2*)(out + (size_t)row1 * CD + n) =
                make_float2(c[ma][nb][2] + bias.x, c[ma][nb][3] + bias.y);
        }
    }
}

// ---------------------------------------------------------------------------
extern "C" void kernel_launch(void* const* d_in, const int* in_sizes, int n_in,
                              void* d_out, int out_size)
{
    const float* x    = (const float*)d_in[0];
    const float* qape = (const float*)d_in[1];
    const float* kape = (const float*)d_in[2];
    const float* pos  = (const float*)d_in[3];
    const float* Wq   = (const float*)d_in[4];
    const float* Wk   = (const float*)d_in[5];
    const float* Wv   = (const float*)d_in[6];
    const float* Wp   = (const float*)d_in[7];
    const float* bp   = (const float*)d_in[8];
    float* out = (float*)d_out;

    cudaFuncSetAttribute(qkv_gemm,  cudaFuncAttributeMaxDynamicSharedMemorySize, GEMM_SMEM);
    cudaFuncSetAttribute(proj_gemm, cudaFuncAttributeMaxDynamicSharedMemorySize, GEMM_SMEM);
    cudaFuncSetAttribute(attn_kernel, cudaFuncAttributeMaxDynamicSharedMemorySize, ATTN_SMEM);

    prep_x<<<ML * CD / (256 * 4), 256>>>(x, qape, kape);
    dim3 wgrid(CD * CD / (256 * 4), 4);
    prep_w<<<wgrid, 256>>>(Wq, Wk, Wv, Wp);

    dim3 gemm_grid(CD / 128, ML / 128, 3);
    qkv_gemm<<<gemm_grid, 256, GEMM_SMEM>>>();

    dim3 attn_grid(LS / 64, BATCH * NH);
    attn_kernel<<<attn_grid, 128, ATTN_SMEM>>>(pos);

    dim3 proj_grid(CD / 128, ML / 128, 1);
    proj_gemm<<<proj_grid, 256, GEMM_SMEM>>>(bp, out);
}

// round 15
// speedup vs baseline: 1.1062x; 1.1062x over previous
#include <cuda_runtime.h>
#include <cuda_bf16.h>
#include <cuda_fp16.h>
#include <cstdint>

#define NH 12
#define HD 64
#define CD 768
#define LS 1024
#define BATCH 4
#define ML (BATCH*LS)
#define ATT_SCALE 0.125f
#define LOGMAX 10.0f

// GEMM-side scratch: bf16 hi/lo pairs.
__device__ __align__(16) __nv_bfloat16 g_xqh[ML*CD], g_xql[ML*CD];  // (x+q_ape)*scale
__device__ __align__(16) __nv_bfloat16 g_xkh[ML*CD], g_xkl[ML*CD];  // x+k_ape
__device__ __align__(16) __nv_bfloat16 g_xvh[ML*CD], g_xvl[ML*CD];  // x
__device__ __align__(16) __nv_bfloat16 g_wqh[CD*CD], g_wql[CD*CD];
__device__ __align__(16) __nv_bfloat16 g_wkh[CD*CD], g_wkl[CD*CD];
__device__ __align__(16) __nv_bfloat16 g_wvh[CD*CD], g_wvl[CD*CD];
__device__ __align__(16) __nv_bfloat16 g_wph[CD*CD], g_wpl[CD*CD];
// Attention-side: Q fp16 hi/lo, K single fp16, V fp16 hi/lo.
__device__ __align__(16) __half g_qh[ML*CD], g_ql[ML*CD];           // [B,H,L,D]
__device__ __align__(16) __half g_kf[ML*CD];
__device__ __align__(16) __half g_vh[ML*CD], g_vl[ML*CD];
__device__ __align__(16) __nv_bfloat16 g_oh[ML*CD], g_ol[ML*CD];    // [B,L,C]

// ---------------- helpers ----------------
__device__ __forceinline__ uint32_t sptr(const void* p) {
    return (uint32_t)__cvta_generic_to_shared(p);
}
__device__ __forceinline__ void bsplit(float x, float y, uint32_t& hp, uint32_t& lp) {
    __nv_bfloat16 hx = __float2bfloat16_rn(x);
    __nv_bfloat16 hy = __float2bfloat16_rn(y);
    float rx = x - __bfloat162float(hx);
    float ry = y - __bfloat162float(hy);
    __nv_bfloat16 lx = __float2bfloat16_rn(rx);
    __nv_bfloat16 ly = __float2bfloat16_rn(ry);
    hp = (uint32_t)__bfloat16_as_ushort(hx) | ((uint32_t)__bfloat16_as_ushort(hy) << 16);
    lp = (uint32_t)__bfloat16_as_ushort(lx) | ((uint32_t)__bfloat16_as_ushort(ly) << 16);
}
__device__ __forceinline__ void hsplit(float x, float y, uint32_t& hp, uint32_t& lp) {
    __half hx = __float2half_rn(x);
    __half hy = __float2half_rn(y);
    float rx = x - __half2float(hx);
    float ry = y - __half2float(hy);
    __half lx = __float2half_rn(rx);
    __half ly = __float2half_rn(ry);
    hp = (uint32_t)__half_as_ushort(hx) | ((uint32_t)__half_as_ushort(hy) << 16);
    lp = (uint32_t)__half_as_ushort(lx) | ((uint32_t)__half_as_ushort(ly) << 16);
}
__device__ __forceinline__ uint32_t packh2(float lo, float hi) {
    uint32_t r;
    asm("cvt.rn.f16x2.f32 %0, %1, %2;" : "=r"(r) : "f"(hi), "f"(lo));
    return r;
}
__device__ __forceinline__ void ldsm4(uint32_t* r, uint32_t a) {
    asm volatile("ldmatrix.sync.aligned.m8n8.x4.shared.b16 {%0,%1,%2,%3},[%4];\n"
                 : "=r"(r[0]), "=r"(r[1]), "=r"(r[2]), "=r"(r[3]) : "r"(a));
}
__device__ __forceinline__ void ldsm4t(uint32_t* r, uint32_t a) {
    asm volatile("ldmatrix.sync.aligned.m8n8.x4.trans.shared.b16 {%0,%1,%2,%3},[%4];\n"
                 : "=r"(r[0]), "=r"(r[1]), "=r"(r[2]), "=r"(r[3]) : "r"(a));
}
__device__ __forceinline__ void mma_bf16(float* c, const uint32_t* a, uint32_t b0, uint32_t b1) {
    asm volatile(
        "mma.sync.aligned.m16n8k16.row.col.f32.bf16.bf16.f32 "
        "{%0,%1,%2,%3},{%4,%5,%6,%7},{%8,%9},{%0,%1,%2,%3};\n"
        : "+f"(c[0]), "+f"(c[1]), "+f"(c[2]), "+f"(c[3])
        : "r"(a[0]), "r"(a[1]), "r"(a[2]), "r"(a[3]), "r"(b0), "r"(b1));
}
__device__ __forceinline__ void mma_f16(float* c, const uint32_t* a, uint32_t b0, uint32_t b1) {
    asm volatile(
        "mma.sync.aligned.m16n8k16.row.col.f32.f16.f16.f32 "
        "{%0,%1,%2,%3},{%4,%5,%6,%7},{%8,%9},{%0,%1,%2,%3};\n"
        : "+f"(c[0]), "+f"(c[1]), "+f"(c[2]), "+f"(c[3])
        : "r"(a[0]), "r"(a[1]), "r"(a[2]), "r"(a[3]), "r"(b0), "r"(b1));
}
__device__ __forceinline__ void cpa16(uint32_t dst, const void* src) {
    asm volatile("cp.async.cg.shared.global [%0], [%1], 16;\n" :: "r"(dst), "l"(src));
}
__device__ __forceinline__ void cp_commit() { asm volatile("cp.async.commit_group;\n"); }
template<int N> __device__ __forceinline__ void cp_wait() {
    asm volatile("cp.async.wait_group %0;\n" :: "n"(N));
}

// ---------------------------------------------------------------------------
// Prep kernels (unchanged)
// ---------------------------------------------------------------------------
__global__ __launch_bounds__(256) void prep_x(
    const float* __restrict__ x,
    const float* __restrict__ qape,
    const float* __restrict__ kape)
{
    const int idx = (blockIdx.x * 256 + threadIdx.x) * 4;
    const int m = idx / CD;
    const int c = idx - m * CD;
    const int l = m & (LS - 1);

    float4 xv = *(const float4*)(x + idx);
    float4 qa = *(const float4*)(qape + (size_t)l * CD + c);
    float4 ka = *(const float4*)(kape + (size_t)l * CD + c);

    uint32_t h0, l0, h1, l1;
    bsplit((xv.x + qa.x) * ATT_SCALE, (xv.y + qa.y) * ATT_SCALE, h0, l0);
    bsplit((xv.z + qa.z) * ATT_SCALE, (xv.w + qa.w) * ATT_SCALE, h1, l1);
    *(uint2*)(g_xqh + idx) = make_uint2(h0, h1);
    *(uint2*)(g_xql + idx) = make_uint2(l0, l1);

    bsplit(xv.x + ka.x, xv.y + ka.y, h0, l0);
    bsplit(xv.z + ka.z, xv.w + ka.w, h1, l1);
    *(uint2*)(g_xkh + idx) = make_uint2(h0, h1);
    *(uint2*)(g_xkl + idx) = make_uint2(l0, l1);

    bsplit(xv.x, xv.y, h0, l0);
    bsplit(xv.z, xv.w, h1, l1);
    *(uint2*)(g_xvh + idx) = make_uint2(h0, h1);
    *(uint2*)(g_xvl + idx) = make_uint2(l0, l1);
}

__global__ __launch_bounds__(256) void prep_w(
    const float* __restrict__ Wq, const float* __restrict__ Wk,
    const float* __restrict__ Wv, const float* __restrict__ Wp)
{
    const int mat = blockIdx.y;
    const float* W = (mat == 0) ? Wq : (mat == 1) ? Wk : (mat == 2) ? Wv : Wp;
    __nv_bfloat16* wh = (mat == 0) ? g_wqh : (mat == 1) ? g_wkh : (mat == 2) ? g_wvh : g_wph;
    __nv_bfloat16* wl = (mat == 0) ? g_wql : (mat == 1) ? g_wkl : (mat == 2) ? g_wvl : g_wpl;

    const int idx = (blockIdx.x * 256 + threadIdx.x) * 4;
    float4 v = *(const float4*)(W + idx);
    uint32_t h0, l0, h1, l1;
    bsplit(v.x, v.y, h0, l0);
    bsplit(v.z, v.w, h1, l1);
    *(uint2*)(wh + idx) = make_uint2(h0, h1);
    *(uint2*)(wl + idx) = make_uint2(l0, l1);
}

// ---------------------------------------------------------------------------
// GEMM: 4-stage cp.async ring, block 128x128, BK=16, 256 thr, warp 64x32.
// ---------------------------------------------------------------------------
#define AST 24
#define GS (128*AST)
#define GIDX(st,row,col) (((st)*128+(row))*AST+(col))
#define GEMM_SMEM (4*4*GS*2)

__global__ __launch_bounds__(256, 2) void qkv_gemm()
{
    extern __shared__ __nv_bfloat16 dsm[];
    __nv_bfloat16* Ah = dsm;
    __nv_bfloat16* Al = dsm + 4*GS;
    __nv_bfloat16* Bh = dsm + 8*GS;
    __nv_bfloat16* Bl = dsm + 12*GS;

    const int which = blockIdx.z;
    const __nv_bfloat16* pAh = (which == 0) ? g_xqh : (which == 1) ? g_xkh : g_xvh;
    const __nv_bfloat16* pAl = (which == 0) ? g_xql : (which == 1) ? g_xkl : g_xvl;
    const __nv_bfloat16* pBh = (which == 0) ? g_wqh : (which == 1) ? g_wkh : g_wvh;
    const __nv_bfloat16* pBl = (which == 0) ? g_wql : (which == 1) ? g_wkl : g_wvl;
    __half* outH = (which == 0) ? g_qh : (which == 1) ? g_kf : g_vh;
    __half* outL = (which == 0) ? g_ql : (which == 1) ? nullptr : g_vl;

    const int tid  = threadIdx.x;
    const int lane = tid & 31;
    const int warp = tid >> 5;
    const int gid  = lane >> 2;
    const int tig  = lane & 3;
    const int wm   = warp >> 2;
    const int wn   = warp & 3;

    const int m0 = blockIdx.y * 128;
    const int n0 = blockIdx.x * 128;
    const int lr = tid >> 1;
    const int lc = (tid & 1) << 3;

    const __nv_bfloat16* ah = pAh + (size_t)(m0 + lr) * CD + lc;
    const __nv_bfloat16* al = pAl + (size_t)(m0 + lr) * CD + lc;
    const __nv_bfloat16* bh = pBh + (size_t)(n0 + lr) * CD + lc;
    const __nv_bfloat16* bl = pBl + (size_t)(n0 + lr) * CD + lc;

    float c[4][4][4];
#pragma unroll
    for (int i = 0; i < 4; i++)
#pragma unroll
        for (int j = 0; j < 4; j++)
#pragma unroll
            for (int v = 0; v < 4; v++) c[i][j][v] = 0.f;

#pragma unroll
    for (int p = 0; p < 3; p++) {
        const int k0 = p * 16;
        cpa16(sptr(&Ah[GIDX(p, lr, lc)]), ah + k0);
        cpa16(sptr(&Al[GIDX(p, lr, lc)]), al + k0);
        cpa16(sptr(&Bh[GIDX(p, lr, lc)]), bh + k0);
        cpa16(sptr(&Bl[GIDX(p, lr, lc)]), bl + k0);
        cp_commit();
    }

    const int arow_s = wm * 64 + (lane & 15);
    const int acol_s = (lane >> 4) * 8;
    const int brow_s = wn * 32 + ((lane >> 4) & 1) * 8 + (lane & 7);
    const int bcol_s = ((lane >> 3) & 1) * 8;

    const int NIT = CD / 16;
    for (int it = 0; it < NIT; ++it) {
        const int st = it & 3;
        if (it < NIT - 2)       cp_wait<2>();
        else if (it == NIT - 2) cp_wait<1>();
        else                    cp_wait<0>();
        __syncthreads();

        if (it + 3 < NIT) {
            const int s2 = (it + 3) & 3;
            const int k0 = (it + 3) * 16;
            cpa16(sptr(&Ah[GIDX(s2, lr, lc)]), ah + k0);
            cpa16(sptr(&Al[GIDX(s2, lr, lc)]), al + k0);
            cpa16(sptr(&Bh[GIDX(s2, lr, lc)]), bh + k0);
            cpa16(sptr(&Bl[GIDX(s2, lr, lc)]), bl + k0);
            cp_commit();
        }

        uint32_t fah[4][4], fal[4][4], fbh[2][4], fbl[2][4];
#pragma unroll
        for (int ma = 0; ma < 4; ma++) {
            ldsm4(fah[ma], sptr(&Ah[GIDX(st, arow_s + ma * 16, acol_s)]));
            ldsm4(fal[ma], sptr(&Al[GIDX(st, arow_s + ma * 16, acol_s)]));
        }
#pragma unroll
        for (int np = 0; np < 2; np++) {
            ldsm4(fbh[np], sptr(&Bh[GIDX(st, brow_s + np * 16, bcol_s)]));
            ldsm4(fbl[np], sptr(&Bl[GIDX(st, brow_s + np * 16, bcol_s)]));
        }
#pragma unroll
        for (int ma = 0; ma < 4; ma++)
#pragma unroll
            for (int nb = 0; nb < 4; nb++) {
                const int np = nb >> 1, sel = (nb & 1) * 2;
                mma_bf16(c[ma][nb], fah[ma], fbh[np][sel], fbh[np][sel + 1]);
                mma_bf16(c[ma][nb], fah[ma], fbl[np][sel], fbl[np][sel + 1]);
                mma_bf16(c[ma][nb], fal[ma], fbh[np][sel], fbh[np][sel + 1]);
            }
    }

    // epilogue -> [B,H,L,D]; Q fp16 hi/lo, K single fp16, V fp16 hi/lo
#pragma unroll
    for (int ma = 0; ma < 4; ma++) {
        int row0 = m0 + wm * 64 + ma * 16 + gid;
        int row1 = row0 + 8;
        int b0i = row0 >> 10, l0 = row0 & (LS - 1);
        int b1i = row1 >> 10, l1 = row1 & (LS - 1);
#pragma unroll
        for (int nb = 0; nb < 4; nb++) {
            int n = n0 + wn * 32 + nb * 8 + 2 * tig;
            int h = n >> 6, d = n & 63;
            size_t o0 = ((size_t)((b0i * NH + h) * LS + l0)) * HD + d;
            size_t o1 = ((size_t)((b1i * NH + h) * LS + l1)) * HD + d;
            if (outL) {
                uint32_t hp, lp;
                hsplit(c[ma][nb][0], c[ma][nb][1], hp, lp);
                *(uint32_t*)(outH + o0) = hp;
                *(uint32_t*)(outL + o0) = lp;
                hsplit(c[ma][nb][2], c[ma][nb][3], hp, lp);
                *(uint32_t*)(outH + o1) = hp;
                *(uint32_t*)(outL + o1) = lp;
            } else {
                *(uint32_t*)(outH + o0) = packh2(c[ma][nb][0], c[ma][nb][1]);
                *(uint32_t*)(outH + o1) = packh2(c[ma][nb][2], c[ma][nb][3]);
            }
        }
    }
}

// ---------------------------------------------------------------------------
// Attention (R13 structure): fixed-max softmax, Q persistent smem, 2-stage
// cp.async KV. S path fp16 (Q hi/lo x K single = 2 MMAs); PV fp16 (P x V hi/lo).
// ---------------------------------------------------------------------------
#define KST 72
// Sb: [2][3][32][KST] fp16 = 27648 B ; Qh/Ql: [64][KST] fp16 = 9216 B each
#define ATTN_SMEM (27648 + 2*9216)
#define SIDX(st,arr,row,col) ((((st)*3+(arr))*32+(row))*KST+(col))

__global__ __launch_bounds__(128, 4) void attn_kernel(const float* __restrict__ pos)
{
    extern __shared__ char asmem[];
    __half* Sb = (__half*)asmem;
    __half* Qh = (__half*)(asmem + 27648);
    __half* Ql = Qh + 64 * KST;

    const int tid  = threadIdx.x;
    const int lane = tid & 31;
    const int warp = tid >> 5;
    const int gid  = lane >> 2;
    const int tig  = lane & 3;

    const int bh = blockIdx.y;
    const int b  = bh / NH;
    const int h  = bh - b * NH;
    const int q0 = blockIdx.x * 64;

    const size_t base = (size_t)bh * LS * HD;

    // ---- prologue: Q into persistent smem ----
    {
        const __half* src = ((warp & 2) ? g_ql : g_qh) +
            base + (size_t)(q0 + (warp & 1) * 32 + lane) * HD;
        __half* dst = ((warp & 2) ? Ql : Qh) + ((warp & 1) * 32 + lane) * KST;
        uint32_t d0 = sptr(dst);
#pragma unroll
        for (int cidx = 0; cidx < 8; cidx++) cpa16(d0 + cidx * 16, src + cidx * 8);
    }
    cp_commit();

    // KV loader: warp 0 -> K (arr 0), warp 1 -> Vh (arr 1), warp 2 -> Vl (arr 2)
    const __half* kvsrc =
        ((warp == 0) ? g_kf : (warp == 1) ? g_vh : g_vl) + base;

    if (warp < 3) {
        const __half* src = kvsrc + (size_t)lane * HD;
        uint32_t d0 = sptr(&Sb[SIDX(0, warp, lane, 0)]);
#pragma unroll
        for (int cidx = 0; cidx < 8; cidx++) cpa16(d0 + cidx * 16, src + cidx * 8);
    }
    cp_commit();

    const int r = warp * 16 + gid;
    const float* pb0 = pos + ((size_t)(h * LS + q0 + r))     * LS + 2 * tig;
    const float* pb1 = pos + ((size_t)(h * LS + q0 + r + 8)) * LS + 2 * tig;

    const int qrow = warp * 16 + (lane & 15);
    const int qc   = (lane >> 4) * 8;

    float o[8][4];
#pragma unroll
    for (int nd = 0; nd < 8; nd++)
#pragma unroll
        for (int v = 0; v < 4; v++) o[nd][v] = 0.f;
    float li[2] = {0.f, 0.f};

    const int krow_s = ((lane >> 4) & 1) * 8 + (lane & 7);
    const int kcol_s = ((lane >> 3) & 1) * 8;
    const int vrow_s = ((lane >> 3) & 1) * 8 + (lane & 7);
    const int vcol_s = ((lane >> 4) & 1) * 8;

    const int NJ = LS / 32;
    for (int i = 0; i < NJ; i++) {
        const int st = i & 1;
        if (i + 1 < NJ) {
            if (warp < 3) {
                const __half* src = kvsrc + (size_t)((i + 1) * 32 + lane) * HD;
                uint32_t d0 = sptr(&Sb[SIDX(st ^ 1, warp, lane, 0)]);
#pragma unroll
                for (int cidx = 0; cidx < 8; cidx++) cpa16(d0 + cidx * 16, src + cidx * 8);
            }
            cp_commit();
            cp_wait<1>();
        } else {
            cp_wait<0>();
        }
        __syncthreads();

        const int j0 = i * 32;
        float2 pv0[4], pv1[4];
#pragma unroll
        for (int nb = 0; nb < 4; nb++) {
            pv0[nb] = *(const float2*)(pb0 + j0 + nb * 8);
            pv1[nb] = *(const float2*)(pb1 + j0 + nb * 8);
        }

        // ---- S = Q K^T (fp16: Q hi/lo x K single) ----
        float s[4][4];
#pragma unroll
        for (int nb = 0; nb < 4; nb++)
#pragma unroll
            for (int v = 0; v < 4; v++) s[nb][v] = 0.f;

#pragma unroll
        for (int kc = 0; kc < 4; kc++) {
            uint32_t qh[4], ql[4];
            ldsm4(qh, sptr(Qh + qrow * KST + kc * 16 + qc));
            ldsm4(ql, sptr(Ql + qrow * KST + kc * 16 + qc));
#pragma unroll
            for (int np = 0; np < 2; np++) {
                uint32_t kf[4];
                ldsm4(kf, sptr(&Sb[SIDX(st, 0, np * 16 + krow_s, kc * 16 + kcol_s)]));
                mma_f16(s[2*np],   qh, kf[0], kf[1]);
                mma_f16(s[2*np],   ql, kf[0], kf[1]);
                mma_f16(s[2*np+1], qh, kf[2], kf[3]);
                mma_f16(s[2*np+1], ql, kf[2], kf[3]);
            }
        }

        // ---- fixed-max softmax: p = exp(s + pos - LOGMAX) ----
#pragma unroll
        for (int nb = 0; nb < 4; nb++) {
            float e0 = __expf(s[nb][0] + pv0[nb].x - LOGMAX);
            float e1 = __expf(s[nb][1] + pv0[nb].y - LOGMAX);
            float e2 = __expf(s[nb][2] + pv1[nb].x - LOGMAX);
            float e3 = __expf(s[nb][3] + pv1[nb].y - LOGMAX);
            s[nb][0] = e0; s[nb][1] = e1; s[nb][2] = e2; s[nb][3] = e3;
            li[0] += e0 + e1;
            li[1] += e2 + e3;
        }

        // ---- P fragments: single fp16 ----
        uint32_t pf[2][4];
#pragma unroll
        for (int kc = 0; kc < 2; kc++) {
            pf[kc][0] = packh2(s[2*kc][0],   s[2*kc][1]);
            pf[kc][1] = packh2(s[2*kc][2],   s[2*kc][3]);
            pf[kc][2] = packh2(s[2*kc+1][0], s[2*kc+1][1]);
            pf[kc][3] = packh2(s[2*kc+1][2], s[2*kc+1][3]);
        }

        // ---- O += P V (fp16: p * (vh + vl)) ----
#pragma unroll
        for (int kc = 0; kc < 2; kc++)
#pragma unroll
            for (int np = 0; np < 4; np++) {
                uint32_t vh[4], vl[4];
                ldsm4t(vh, sptr(&Sb[SIDX(st, 1, kc * 16 + vrow_s, np * 16 + vcol_s)]));
                ldsm4t(vl, sptr(&Sb[SIDX(st, 2, kc * 16 + vrow_s, np * 16 + vcol_s)]));
                mma_f16(o[2*np],   pf[kc], vh[0], vh[1]);
                mma_f16(o[2*np],   pf[kc], vl[0], vl[1]);
                mma_f16(o[2*np+1], pf[kc], vh[2], vh[3]);
                mma_f16(o[2*np+1], pf[kc], vl[2], vl[3]);
            }

        __syncthreads();
    }

#pragma unroll
    for (int rp = 0; rp < 2; rp++) {
        li[rp] += __shfl_xor_sync(0xffffffffu, li[rp], 1);
        li[rp] += __shfl_xor_sync(0xffffffffu, li[rp], 2);
    }
    float inv0 = 1.0f / li[0];
    float inv1 = 1.0f / li[1];
#pragma unroll
    for (int nd = 0; nd < 8; nd++) {
        int d = nd * 8 + 2 * tig;
        size_t o0 = ((size_t)(b * LS + q0 + r)) * CD + h * HD + d;
        size_t o1 = ((size_t)(b * LS + q0 + r + 8)) * CD + h * HD + d;
        uint32_t hp, lp;
        bsplit(o[nd][0] * inv0, o[nd][1] * inv0, hp, lp);
        *(uint32_t*)(g_oh + o0) = hp;
        *(uint32_t*)(g_ol + o0) = lp;
        bsplit(o[nd][2] * inv1, o[nd][3] * inv1, hp, lp);
        *(uint32_t*)(g_oh + o1) = hp;
        *(uint32_t*)(g_ol + o1) = lp;
    }
}

// ---------------------------------------------------------------------------
// Output projection: 4-stage ring (bf16 split-3, unchanged).
// ---------------------------------------------------------------------------
__global__ __launch_bounds__(256, 2) void proj_gemm(
    const float* __restrict__ bp,
    float* __restrict__ out)
{
    extern __shared__ __nv_bfloat16 dsm[];
    __nv_bfloat16* Ah = dsm;
    __nv_bfloat16* Al = dsm + 4*GS;
    __nv_bfloat16* Bh = dsm + 8*GS;
    __nv_bfloat16* Bl = dsm + 12*GS;

    const int tid  = threadIdx.x;
    const int lane = tid & 31;
    const int warp = tid >> 5;
    const int gid  = lane >> 2;
    const int tig  = lane & 3;
    const int wm   = warp >> 2;
    const int wn   = warp & 3;

    const int m0 = blockIdx.y * 128;
    const int n0 = blockIdx.x * 128;
    const int lr = tid >> 1;
    const int lc = (tid & 1) << 3;

    const __nv_bfloat16* ah = g_oh  + (size_t)(m0 + lr) * CD + lc;
    const __nv_bfloat16* al = g_ol  + (size_t)(m0 + lr) * CD + lc;
    const __nv_bfloat16* bh = g_wph + (size_t)(n0 + lr) * CD + lc;
    const __nv_bfloat16* bl = g_wpl + (size_t)(n0 + lr) * CD + lc;

    float c[4][4][4];
#pragma unroll
    for (int i = 0; i < 4; i++)
#pragma unroll
        for (int j = 0; j < 4; j++)
#pragma unroll
            for (int v = 0; v < 4; v++) c[i][j][v] = 0.f;

#pragma unroll
    for (int p = 0; p < 3; p++) {
        const int k0 = p * 16;
        cpa16(sptr(&Ah[GIDX(p, lr, lc)]), ah + k0);
        cpa16(sptr(&Al[GIDX(p, lr, lc)]), al + k0);
        cpa16(sptr(&Bh[GIDX(p, lr, lc)]), bh + k0);
        cpa16(sptr(&Bl[GIDX(p, lr, lc)]), bl + k0);
        cp_commit();
    }

    const int arow_s = wm * 64 + (lane & 15);
    const int acol_s = (lane >> 4) * 8;
    const int brow_s = wn * 32 + ((lane >> 4) & 1) * 8 + (lane & 7);
    const int bcol_s = ((lane >> 3) & 1) * 8;

    const int NIT = CD / 16;
    for (int it = 0; it < NIT; ++it) {
        const int st = it & 3;
        if (it < NIT - 2)       cp_wait<2>();
        else if (it == NIT - 2) cp_wait<1>();
        else                    cp_wait<0>();
        __syncthreads();

        if (it + 3 < NIT) {
            const int s2 = (it + 3) & 3;
            const int k0 = (it + 3) * 16;
            cpa16(sptr(&Ah[GIDX(s2, lr, lc)]), ah + k0);
            cpa16(sptr(&Al[GIDX(s2, lr, lc)]), al + k0);
            cpa16(sptr(&Bh[GIDX(s2, lr, lc)]), bh + k0);
            cpa16(sptr(&Bl[GIDX(s2, lr, lc)]), bl + k0);
            cp_commit();
        }

        uint32_t fah[4][4], fal[4][4], fbh[2][4], fbl[2][4];
#pragma unroll
        for (int ma = 0; ma < 4; ma++) {
            ldsm4(fah[ma], sptr(&Ah[GIDX(st, arow_s + ma * 16, acol_s)]));
            ldsm4(fal[ma], sptr(&Al[GIDX(st, arow_s + ma * 16, acol_s)]));
        }
#pragma unroll
        for (int np = 0; np < 2; np++) {
            ldsm4(fbh[np], sptr(&Bh[GIDX(st, brow_s + np * 16, bcol_s)]));
            ldsm4(fbl[np], sptr(&Bl[GIDX(st, brow_s + np * 16, bcol_s)]));
        }
#pragma unroll
        for (int ma = 0; ma < 4; ma++)
#pragma unroll
            for (int nb = 0; nb < 4; nb++) {
                const int np = nb >> 1, sel = (nb & 1) * 2;
                mma_bf16(c[ma][nb], fah[ma], fbh[np][sel], fbh[np][sel + 1]);
                mma_bf16(c[ma][nb], fah[ma], fbl[np][sel], fbl[np][sel + 1]);
                mma_bf16(c[ma][nb], fal[ma], fbh[np][sel], fbh[np][sel + 1]);
            }
    }

#pragma unroll
    for (int ma = 0; ma < 4; ma++) {
        int row0 = m0 + wm * 64 + ma * 16 + gid;
        int row1 = row0 + 8;
#pragma unroll
        for (int nb = 0; nb < 4; nb++) {
            int n = n0 + wn * 32 + nb * 8 + 2 * tig;
            float2 bias = *(const float2*)(bp + n);
            *(float2*)(out + (size_t)row0 * CD + n) =
                make_float2(c[ma][nb][0] + bias.x, c[ma][nb][1] + bias.y);
            *(float2*)(out + (size_t)row1 * CD + n) =
                make_float2(c[ma][nb][2] + bias.x, c[ma][nb][3] + bias.y);
        }
    }
}

// ---------------------------------------------------------------------------
extern "C" void kernel_launch(void* const* d_in, const int* in_sizes, int n_in,
                              void* d_out, int out_size)
{
    const float* x    = (const float*)d_in[0];
    const float* qape = (const float*)d_in[1];
    const float* kape = (const float*)d_in[2];
    const float* pos  = (const float*)d_in[3];
    const float* Wq   = (const float*)d_in[4];
    const float* Wk   = (const float*)d_in[5];
    const float* Wv   = (const float*)d_in[6];
    const float* Wp   = (const float*)d_in[7];
    const float* bp   = (const float*)d_in[8];
    float* out = (float*)d_out;

    cudaFuncSetAttribute(qkv_gemm,  cudaFuncAttributeMaxDynamicSharedMemorySize, GEMM_SMEM);
    cudaFuncSetAttribute(proj_gemm, cudaFuncAttributeMaxDynamicSharedMemorySize, GEMM_SMEM);
    cudaFuncSetAttribute(attn_kernel, cudaFuncAttributeMaxDynamicSharedMemorySize, ATTN_SMEM);

    prep_x<<<ML * CD / (256 * 4), 256>>>(x, qape, kape);
    dim3 wgrid(CD * CD / (256 * 4), 4);
    prep_w<<<wgrid, 256>>>(Wq, Wk, Wv, Wp);

    dim3 gemm_grid(CD / 128, ML / 128, 3);
    qkv_gemm<<<gemm_grid, 256, GEMM_SMEM>>>();

    dim3 attn_grid(LS / 64, BATCH * NH);
    attn_kernel<<<attn_grid, 128, ATTN_SMEM>>>(pos);

    dim3 proj_grid(CD / 128, ML / 128, 1);
    proj_gemm<<<proj_grid, 256, GEMM_SMEM>>>(bp, out);
}

// round 16
// speedup vs baseline: 1.2333x; 1.1149x over previous
#include <cuda_runtime.h>
#include <cuda_bf16.h>
#include <cuda_fp16.h>
#include <cstdint>

#define NH 12
#define HD 64
#define CD 768
#define LS 1024
#define BATCH 4
#define ML (BATCH*LS)
#define ATT_SCALE 0.125f
#define LOGMAX 10.0f

// GEMM-side scratch: bf16 hi/lo pairs.
__device__ __align__(16) __nv_bfloat16 g_xqh[ML*CD], g_xql[ML*CD];  // (x+q_ape)*scale
__device__ __align__(16) __nv_bfloat16 g_xkh[ML*CD], g_xkl[ML*CD];  // x+k_ape
__device__ __align__(16) __nv_bfloat16 g_xvh[ML*CD], g_xvl[ML*CD];  // x
__device__ __align__(16) __nv_bfloat16 g_wqh[CD*CD], g_wql[CD*CD];
__device__ __align__(16) __nv_bfloat16 g_wkh[CD*CD], g_wkl[CD*CD];
__device__ __align__(16) __nv_bfloat16 g_wvh[CD*CD], g_wvl[CD*CD];
__device__ __align__(16) __nv_bfloat16 g_wph[CD*CD], g_wpl[CD*CD];
// Attention-side: Q, K, V all single fp16.
__device__ __align__(16) __half g_qf[ML*CD];                        // [B,H,L,D]
__device__ __align__(16) __half g_kf[ML*CD];
__device__ __align__(16) __half g_vf[ML*CD];
__device__ __align__(16) __nv_bfloat16 g_oh[ML*CD], g_ol[ML*CD];    // [B,L,C]

// ---------------- helpers ----------------
__device__ __forceinline__ uint32_t sptr(const void* p) {
    return (uint32_t)__cvta_generic_to_shared(p);
}
__device__ __forceinline__ void bsplit(float x, float y, uint32_t& hp, uint32_t& lp) {
    __nv_bfloat16 hx = __float2bfloat16_rn(x);
    __nv_bfloat16 hy = __float2bfloat16_rn(y);
    float rx = x - __bfloat162float(hx);
    float ry = y - __bfloat162float(hy);
    __nv_bfloat16 lx = __float2bfloat16_rn(rx);
    __nv_bfloat16 ly = __float2bfloat16_rn(ry);
    hp = (uint32_t)__bfloat16_as_ushort(hx) | ((uint32_t)__bfloat16_as_ushort(hy) << 16);
    lp = (uint32_t)__bfloat16_as_ushort(lx) | ((uint32_t)__bfloat16_as_ushort(ly) << 16);
}
__device__ __forceinline__ uint32_t packh2(float lo, float hi) {
    uint32_t r;
    asm("cvt.rn.f16x2.f32 %0, %1, %2;" : "=r"(r) : "f"(hi), "f"(lo));
    return r;
}
__device__ __forceinline__ void ldsm4(uint32_t* r, uint32_t a) {
    asm volatile("ldmatrix.sync.aligned.m8n8.x4.shared.b16 {%0,%1,%2,%3},[%4];\n"
                 : "=r"(r[0]), "=r"(r[1]), "=r"(r[2]), "=r"(r[3]) : "r"(a));
}
__device__ __forceinline__ void ldsm4t(uint32_t* r, uint32_t a) {
    asm volatile("ldmatrix.sync.aligned.m8n8.x4.trans.shared.b16 {%0,%1,%2,%3},[%4];\n"
                 : "=r"(r[0]), "=r"(r[1]), "=r"(r[2]), "=r"(r[3]) : "r"(a));
}
__device__ __forceinline__ void mma_bf16(float* c, const uint32_t* a, uint32_t b0, uint32_t b1) {
    asm volatile(
        "mma.sync.aligned.m16n8k16.row.col.f32.bf16.bf16.f32 "
        "{%0,%1,%2,%3},{%4,%5,%6,%7},{%8,%9},{%0,%1,%2,%3};\n"
        : "+f"(c[0]), "+f"(c[1]), "+f"(c[2]), "+f"(c[3])
        : "r"(a[0]), "r"(a[1]), "r"(a[2]), "r"(a[3]), "r"(b0), "r"(b1));
}
__device__ __forceinline__ void mma_f16(float* c, const uint32_t* a, uint32_t b0, uint32_t b1) {
    asm volatile(
        "mma.sync.aligned.m16n8k16.row.col.f32.f16.f16.f32 "
        "{%0,%1,%2,%3},{%4,%5,%6,%7},{%8,%9},{%0,%1,%2,%3};\n"
        : "+f"(c[0]), "+f"(c[1]), "+f"(c[2]), "+f"(c[3])
        : "r"(a[0]), "r"(a[1]), "r"(a[2]), "r"(a[3]), "r"(b0), "r"(b1));
}
__device__ __forceinline__ void cpa16(uint32_t dst, const void* src) {
    asm volatile("cp.async.cg.shared.global [%0], [%1], 16;\n" :: "r"(dst), "l"(src));
}
__device__ __forceinline__ void cp_commit() { asm volatile("cp.async.commit_group;\n"); }
template<int N> __device__ __forceinline__ void cp_wait() {
    asm volatile("cp.async.wait_group %0;\n" :: "n"(N));
}

// ---------------------------------------------------------------------------
// Prep kernels (unchanged)
// ---------------------------------------------------------------------------
__global__ __launch_bounds__(256) void prep_x(
    const float* __restrict__ x,
    const float* __restrict__ qape,
    const float* __restrict__ kape)
{
    const int idx = (blockIdx.x * 256 + threadIdx.x) * 4;
    const int m = idx / CD;
    const int c = idx - m * CD;
    const int l = m & (LS - 1);

    float4 xv = *(const float4*)(x + idx);
    float4 qa = *(const float4*)(qape + (size_t)l * CD + c);
    float4 ka = *(const float4*)(kape + (size_t)l * CD + c);

    uint32_t h0, l0, h1, l1;
    bsplit((xv.x + qa.x) * ATT_SCALE, (xv.y + qa.y) * ATT_SCALE, h0, l0);
    bsplit((xv.z + qa.z) * ATT_SCALE, (xv.w + qa.w) * ATT_SCALE, h1, l1);
    *(uint2*)(g_xqh + idx) = make_uint2(h0, h1);
    *(uint2*)(g_xql + idx) = make_uint2(l0, l1);

    bsplit(xv.x + ka.x, xv.y + ka.y, h0, l0);
    bsplit(xv.z + ka.z, xv.w + ka.w, h1, l1);
    *(uint2*)(g_xkh + idx) = make_uint2(h0, h1);
    *(uint2*)(g_xkl + idx) = make_uint2(l0, l1);

    bsplit(xv.x, xv.y, h0, l0);
    bsplit(xv.z, xv.w, h1, l1);
    *(uint2*)(g_xvh + idx) = make_uint2(h0, h1);
    *(uint2*)(g_xvl + idx) = make_uint2(l0, l1);
}

__global__ __launch_bounds__(256) void prep_w(
    const float* __restrict__ Wq, const float* __restrict__ Wk,
    const float* __restrict__ Wv, const float* __restrict__ Wp)
{
    const int mat = blockIdx.y;
    const float* W = (mat == 0) ? Wq : (mat == 1) ? Wk : (mat == 2) ? Wv : Wp;
    __nv_bfloat16* wh = (mat == 0) ? g_wqh : (mat == 1) ? g_wkh : (mat == 2) ? g_wvh : g_wph;
    __nv_bfloat16* wl = (mat == 0) ? g_wql : (mat == 1) ? g_wkl : (mat == 2) ? g_wvl : g_wpl;

    const int idx = (blockIdx.x * 256 + threadIdx.x) * 4;
    float4 v = *(const float4*)(W + idx);
    uint32_t h0, l0, h1, l1;
    bsplit(v.x, v.y, h0, l0);
    bsplit(v.z, v.w, h1, l1);
    *(uint2*)(wh + idx) = make_uint2(h0, h1);
    *(uint2*)(wl + idx) = make_uint2(l0, l1);
}

// ---------------------------------------------------------------------------
// GEMM: 4-stage cp.async ring, block 128x128, BK=16, 256 thr, warp 64x32.
// ---------------------------------------------------------------------------
#define AST 24
#define GS (128*AST)
#define GIDX(st,row,col) (((st)*128+(row))*AST+(col))
#define GEMM_SMEM (4*4*GS*2)

__global__ __launch_bounds__(256, 2) void qkv_gemm()
{
    extern __shared__ __nv_bfloat16 dsm[];
    __nv_bfloat16* Ah = dsm;
    __nv_bfloat16* Al = dsm + 4*GS;
    __nv_bfloat16* Bh = dsm + 8*GS;
    __nv_bfloat16* Bl = dsm + 12*GS;

    const int which = blockIdx.z;
    const __nv_bfloat16* pAh = (which == 0) ? g_xqh : (which == 1) ? g_xkh : g_xvh;
    const __nv_bfloat16* pAl = (which == 0) ? g_xql : (which == 1) ? g_xkl : g_xvl;
    const __nv_bfloat16* pBh = (which == 0) ? g_wqh : (which == 1) ? g_wkh : g_wvh;
    const __nv_bfloat16* pBl = (which == 0) ? g_wql : (which == 1) ? g_wkl : g_wvl;
    __half* outH = (which == 0) ? g_qf : (which == 1) ? g_kf : g_vf;

    const int tid  = threadIdx.x;
    const int lane = tid & 31;
    const int warp = tid >> 5;
    const int gid  = lane >> 2;
    const int tig  = lane & 3;
    const int wm   = warp >> 2;
    const int wn   = warp & 3;

    const int m0 = blockIdx.y * 128;
    const int n0 = blockIdx.x * 128;
    const int lr = tid >> 1;
    const int lc = (tid & 1) << 3;

    const __nv_bfloat16* ah = pAh + (size_t)(m0 + lr) * CD + lc;
    const __nv_bfloat16* al = pAl + (size_t)(m0 + lr) * CD + lc;
    const __nv_bfloat16* bh = pBh + (size_t)(n0 + lr) * CD + lc;
    const __nv_bfloat16* bl = pBl + (size_t)(n0 + lr) * CD + lc;

    float c[4][4][4];
#pragma unroll
    for (int i = 0; i < 4; i++)
#pragma unroll
        for (int j = 0; j < 4; j++)
#pragma unroll
            for (int v = 0; v < 4; v++) c[i][j][v] = 0.f;

#pragma unroll
    for (int p = 0; p < 3; p++) {
        const int k0 = p * 16;
        cpa16(sptr(&Ah[GIDX(p, lr, lc)]), ah + k0);
        cpa16(sptr(&Al[GIDX(p, lr, lc)]), al + k0);
        cpa16(sptr(&Bh[GIDX(p, lr, lc)]), bh + k0);
        cpa16(sptr(&Bl[GIDX(p, lr, lc)]), bl + k0);
        cp_commit();
    }

    const int arow_s = wm * 64 + (lane & 15);
    const int acol_s = (lane >> 4) * 8;
    const int brow_s = wn * 32 + ((lane >> 4) & 1) * 8 + (lane & 7);
    const int bcol_s = ((lane >> 3) & 1) * 8;

    const int NIT = CD / 16;
    for (int it = 0; it < NIT; ++it) {
        const int st = it & 3;
        if (it < NIT - 2)       cp_wait<2>();
        else if (it == NIT - 2) cp_wait<1>();
        else                    cp_wait<0>();
        __syncthreads();

        if (it + 3 < NIT) {
            const int s2 = (it + 3) & 3;
            const int k0 = (it + 3) * 16;
            cpa16(sptr(&Ah[GIDX(s2, lr, lc)]), ah + k0);
            cpa16(sptr(&Al[GIDX(s2, lr, lc)]), al + k0);
            cpa16(sptr(&Bh[GIDX(s2, lr, lc)]), bh + k0);
            cpa16(sptr(&Bl[GIDX(s2, lr, lc)]), bl + k0);
            cp_commit();
        }

        uint32_t fah[4][4], fal[4][4], fbh[2][4], fbl[2][4];
#pragma unroll
        for (int ma = 0; ma < 4; ma++) {
            ldsm4(fah[ma], sptr(&Ah[GIDX(st, arow_s + ma * 16, acol_s)]));
            ldsm4(fal[ma], sptr(&Al[GIDX(st, arow_s + ma * 16, acol_s)]));
        }
#pragma unroll
        for (int np = 0; np < 2; np++) {
            ldsm4(fbh[np], sptr(&Bh[GIDX(st, brow_s + np * 16, bcol_s)]));
            ldsm4(fbl[np], sptr(&Bl[GIDX(st, brow_s + np * 16, bcol_s)]));
        }
#pragma unroll
        for (int ma = 0; ma < 4; ma++)
#pragma unroll
            for (int nb = 0; nb < 4; nb++) {
                const int np = nb >> 1, sel = (nb & 1) * 2;
                mma_bf16(c[ma][nb], fah[ma], fbh[np][sel], fbh[np][sel + 1]);
                mma_bf16(c[ma][nb], fah[ma], fbl[np][sel], fbl[np][sel + 1]);
                mma_bf16(c[ma][nb], fal[ma], fbh[np][sel], fbh[np][sel + 1]);
            }
    }

    // epilogue -> [B,H,L,D]; Q/K/V all single fp16
#pragma unroll
    for (int ma = 0; ma < 4; ma++) {
        int row0 = m0 + wm * 64 + ma * 16 + gid;
        int row1 = row0 + 8;
        int b0i = row0 >> 10, l0 = row0 & (LS - 1);
        int b1i = row1 >> 10, l1 = row1 & (LS - 1);
#pragma unroll
        for (int nb = 0; nb < 4; nb++) {
            int n = n0 + wn * 32 + nb * 8 + 2 * tig;
            int h = n >> 6, d = n & 63;
            size_t o0 = ((size_t)((b0i * NH + h) * LS + l0)) * HD + d;
            size_t o1 = ((size_t)((b1i * NH + h) * LS + l1)) * HD + d;
            *(uint32_t*)(outH + o0) = packh2(c[ma][nb][0], c[ma][nb][1]);
            *(uint32_t*)(outH + o1) = packh2(c[ma][nb][2], c[ma][nb][3]);
        }
    }
}

// ---------------------------------------------------------------------------
// Attention: fixed-max softmax, Q persistent smem (single fp16), 2-stage
// cp.async KV (K, V single fp16). S: q x k = 1 MMA; PV: p x v = 1 MMA.
// ---------------------------------------------------------------------------
#define KST 72
// Sb: [2][2][32][KST] fp16 = 18432 B ; Qs: [64][KST] fp16 = 9216 B
#define ATTN_SMEM (18432 + 9216)
#define SIDX(st,arr,row,col) ((((st)*2+(arr))*32+(row))*KST+(col))

__global__ __launch_bounds__(128, 4) void attn_kernel(const float* __restrict__ pos)
{
    extern __shared__ char asmem[];
    __half* Sb = (__half*)asmem;
    __half* Qs = (__half*)(asmem + 18432);

    const int tid  = threadIdx.x;
    const int lane = tid & 31;
    const int warp = tid >> 5;
    const int gid  = lane >> 2;
    const int tig  = lane & 3;

    const int bh = blockIdx.y;
    const int b  = bh / NH;
    const int h  = bh - b * NH;
    const int q0 = blockIdx.x * 64;

    const size_t base = (size_t)bh * LS * HD;

    // ---- prologue: Q into persistent smem (all 128 threads) ----
    {
        const int qr = tid >> 1;
        const int qo = (tid & 1) * 32;
        const __half* src = g_qf + base + (size_t)(q0 + qr) * HD + qo;
        uint32_t d0 = sptr(Qs + qr * KST + qo);
#pragma unroll
        for (int cidx = 0; cidx < 4; cidx++) cpa16(d0 + cidx * 16, src + cidx * 8);
    }
    cp_commit();

    // KV loader: warp 0 -> K (arr 0), warp 1 -> V (arr 1)
    const __half* kvsrc = ((warp == 0) ? g_kf : g_vf) + base;

    if (warp < 2) {
        const __half* src = kvsrc + (size_t)lane * HD;
        uint32_t d0 = sptr(&Sb[SIDX(0, warp, lane, 0)]);
#pragma unroll
        for (int cidx = 0; cidx < 8; cidx++) cpa16(d0 + cidx * 16, src + cidx * 8);
    }
    cp_commit();

    const int r = warp * 16 + gid;
    const float* pb0 = pos + ((size_t)(h * LS + q0 + r))     * LS + 2 * tig;
    const float* pb1 = pos + ((size_t)(h * LS + q0 + r + 8)) * LS + 2 * tig;

    const int qrow = warp * 16 + (lane & 15);
    const int qc   = (lane >> 4) * 8;

    float o[8][4];
#pragma unroll
    for (int nd = 0; nd < 8; nd++)
#pragma unroll
        for (int v = 0; v < 4; v++) o[nd][v] = 0.f;
    float li[2] = {0.f, 0.f};

    const int krow_s = ((lane >> 4) & 1) * 8 + (lane & 7);
    const int kcol_s = ((lane >> 3) & 1) * 8;
    const int vrow_s = ((lane >> 3) & 1) * 8 + (lane & 7);
    const int vcol_s = ((lane >> 4) & 1) * 8;

    const int NJ = LS / 32;
    for (int i = 0; i < NJ; i++) {
        const int st = i & 1;
        if (i + 1 < NJ) {
            if (warp < 2) {
                const __half* src = kvsrc + (size_t)((i + 1) * 32 + lane) * HD;
                uint32_t d0 = sptr(&Sb[SIDX(st ^ 1, warp, lane, 0)]);
#pragma unroll
                for (int cidx = 0; cidx < 8; cidx++) cpa16(d0 + cidx * 16, src + cidx * 8);
            }
            cp_commit();
            cp_wait<1>();
        } else {
            cp_wait<0>();
        }
        __syncthreads();

        const int j0 = i * 32;
        float2 pv0[4], pv1[4];
#pragma unroll
        for (int nb = 0; nb < 4; nb++) {
            pv0[nb] = *(const float2*)(pb0 + j0 + nb * 8);
            pv1[nb] = *(const float2*)(pb1 + j0 + nb * 8);
        }

        // ---- S = Q K^T (single fp16 x single fp16) ----
        float s[4][4];
#pragma unroll
        for (int nb = 0; nb < 4; nb++)
#pragma unroll
            for (int v = 0; v < 4; v++) s[nb][v] = 0.f;

#pragma unroll
        for (int kc = 0; kc < 4; kc++) {
            uint32_t qf[4];
            ldsm4(qf, sptr(Qs + qrow * KST + kc * 16 + qc));
#pragma unroll
            for (int np = 0; np < 2; np++) {
                uint32_t kf[4];
                ldsm4(kf, sptr(&Sb[SIDX(st, 0, np * 16 + krow_s, kc * 16 + kcol_s)]));
                mma_f16(s[2*np],   qf, kf[0], kf[1]);
                mma_f16(s[2*np+1], qf, kf[2], kf[3]);
            }
        }

        // ---- fixed-max softmax: p = exp(s + pos - LOGMAX) ----
#pragma unroll
        for (int nb = 0; nb < 4; nb++) {
            float e0 = __expf(s[nb][0] + pv0[nb].x - LOGMAX);
            float e1 = __expf(s[nb][1] + pv0[nb].y - LOGMAX);
            float e2 = __expf(s[nb][2] + pv1[nb].x - LOGMAX);
            float e3 = __expf(s[nb][3] + pv1[nb].y - LOGMAX);
            s[nb][0] = e0; s[nb][1] = e1; s[nb][2] = e2; s[nb][3] = e3;
            li[0] += e0 + e1;
            li[1] += e2 + e3;
        }

        // ---- P fragments: single fp16 ----
        uint32_t pf[2][4];
#pragma unroll
        for (int kc = 0; kc < 2; kc++) {
            pf[kc][0] = packh2(s[2*kc][0],   s[2*kc][1]);
            pf[kc][1] = packh2(s[2*kc][2],   s[2*kc][3]);
            pf[kc][2] = packh2(s[2*kc+1][0], s[2*kc+1][1]);
            pf[kc][3] = packh2(s[2*kc+1][2], s[2*kc+1][3]);
        }

        // ---- O += P V (single fp16 V) ----
#pragma unroll
        for (int kc = 0; kc < 2; kc++)
#pragma unroll
            for (int np = 0; np < 4; np++) {
                uint32_t vf[4];
                ldsm4t(vf, sptr(&Sb[SIDX(st, 1, kc * 16 + vrow_s, np * 16 + vcol_s)]));
                mma_f16(o[2*np],   pf[kc], vf[0], vf[1]);
                mma_f16(o[2*np+1], pf[kc], vf[2], vf[3]);
            }

        __syncthreads();
    }

#pragma unroll
    for (int rp = 0; rp < 2; rp++) {
        li[rp] += __shfl_xor_sync(0xffffffffu, li[rp], 1);
        li[rp] += __shfl_xor_sync(0xffffffffu, li[rp], 2);
    }
    float inv0 = 1.0f / li[0];
    float inv1 = 1.0f / li[1];
#pragma unroll
    for (int nd = 0; nd < 8; nd++) {
        int d = nd * 8 + 2 * tig;
        size_t o0 = ((size_t)(b * LS + q0 + r)) * CD + h * HD + d;
        size_t o1 = ((size_t)(b * LS + q0 + r + 8)) * CD + h * HD + d;
        uint32_t hp, lp;
        bsplit(o[nd][0] * inv0, o[nd][1] * inv0, hp, lp);
        *(uint32_t*)(g_oh + o0) = hp;
        *(uint32_t*)(g_ol + o0) = lp;
        bsplit(o[nd][2] * inv1, o[nd][3] * inv1, hp, lp);
        *(uint32_t*)(g_oh + o1) = hp;
        *(uint32_t*)(g_ol + o1) = lp;
    }
}

// ---------------------------------------------------------------------------
// Output projection: 4-stage ring (bf16 split-3, unchanged).
// ---------------------------------------------------------------------------
__global__ __launch_bounds__(256, 2) void proj_gemm(
    const float* __restrict__ bp,
    float* __restrict__ out)
{
    extern __shared__ __nv_bfloat16 dsm[];
    __nv_bfloat16* Ah = dsm;
    __nv_bfloat16* Al = dsm + 4*GS;
    __nv_bfloat16* Bh = dsm + 8*GS;
    __nv_bfloat16* Bl = dsm + 12*GS;

    const int tid  = threadIdx.x;
    const int lane = tid & 31;
    const int warp = tid >> 5;
    const int gid  = lane >> 2;
    const int tig  = lane & 3;
    const int wm   = warp >> 2;
    const int wn   = warp & 3;

    const int m0 = blockIdx.y * 128;
    const int n0 = blockIdx.x * 128;
    const int lr = tid >> 1;
    const int lc = (tid & 1) << 3;

    const __nv_bfloat16* ah = g_oh  + (size_t)(m0 + lr) * CD + lc;
    const __nv_bfloat16* al = g_ol  + (size_t)(m0 + lr) * CD + lc;
    const __nv_bfloat16* bh = g_wph + (size_t)(n0 + lr) * CD + lc;
    const __nv_bfloat16* bl = g_wpl + (size_t)(n0 + lr) * CD + lc;

    float c[4][4][4];
#pragma unroll
    for (int i = 0; i < 4; i++)
#pragma unroll
        for (int j = 0; j < 4; j++)
#pragma unroll
            for (int v = 0; v < 4; v++) c[i][j][v] = 0.f;

#pragma unroll
    for (int p = 0; p < 3; p++) {
        const int k0 = p * 16;
        cpa16(sptr(&Ah[GIDX(p, lr, lc)]), ah + k0);
        cpa16(sptr(&Al[GIDX(p, lr, lc)]), al + k0);
        cpa16(sptr(&Bh[GIDX(p, lr, lc)]), bh + k0);
        cpa16(sptr(&Bl[GIDX(p, lr, lc)]), bl + k0);
        cp_commit();
    }

    const int arow_s = wm * 64 + (lane & 15);
    const int acol_s = (lane >> 4) * 8;
    const int brow_s = wn * 32 + ((lane >> 4) & 1) * 8 + (lane & 7);
    const int bcol_s = ((lane >> 3) & 1) * 8;

    const int NIT = CD / 16;
    for (int it = 0; it < NIT; ++it) {
        const int st = it & 3;
        if (it < NIT - 2)       cp_wait<2>();
        else if (it == NIT - 2) cp_wait<1>();
        else                    cp_wait<0>();
        __syncthreads();

        if (it + 3 < NIT) {
            const int s2 = (it + 3) & 3;
            const int k0 = (it + 3) * 16;
            cpa16(sptr(&Ah[GIDX(s2, lr, lc)]), ah + k0);
            cpa16(sptr(&Al[GIDX(s2, lr, lc)]), al + k0);
            cpa16(sptr(&Bh[GIDX(s2, lr, lc)]), bh + k0);
            cpa16(sptr(&Bl[GIDX(s2, lr, lc)]), bl + k0);
            cp_commit();
        }

        uint32_t fah[4][4], fal[4][4], fbh[2][4], fbl[2][4];
#pragma unroll
        for (int ma = 0; ma < 4; ma++) {
            ldsm4(fah[ma], sptr(&Ah[GIDX(st, arow_s + ma * 16, acol_s)]));
            ldsm4(fal[ma], sptr(&Al[GIDX(st, arow_s + ma * 16, acol_s)]));
        }
#pragma unroll
        for (int np = 0; np < 2; np++) {
            ldsm4(fbh[np], sptr(&Bh[GIDX(st, brow_s + np * 16, bcol_s)]));
            ldsm4(fbl[np], sptr(&Bl[GIDX(st, brow_s + np * 16, bcol_s)]));
        }
#pragma unroll
        for (int ma = 0; ma < 4; ma++)
#pragma unroll
            for (int nb = 0; nb < 4; nb++) {
                const int np = nb >> 1, sel = (nb & 1) * 2;
                mma_bf16(c[ma][nb], fah[ma], fbh[np][sel], fbh[np][sel + 1]);
                mma_bf16(c[ma][nb], fah[ma], fbl[np][sel], fbl[np][sel + 1]);
                mma_bf16(c[ma][nb], fal[ma], fbh[np][sel], fbh[np][sel + 1]);
            }
    }

#pragma unroll
    for (int ma = 0; ma < 4; ma++) {
        int row0 = m0 + wm * 64 + ma * 16 + gid;
        int row1 = row0 + 8;
#pragma unroll
        for (int nb = 0; nb < 4; nb++) {
            int n = n0 + wn * 32 + nb * 8 + 2 * tig;
            float2 bias = *(const float2*)(bp + n);
            *(float2*)(out + (size_t)row0 * CD + n) =
                make_float2(c[ma][nb][0] + bias.x, c[ma][nb][1] + bias.y);
            *(float2*)(out + (size_t)row1 * CD + n) =
                make_float2(c[ma][nb][2] + bias.x, c[ma][nb][3] + bias.y);
        }
    }
}

// ---------------------------------------------------------------------------
extern "C" void kernel_launch(void* const* d_in, const int* in_sizes, int n_in,
                              void* d_out, int out_size)
{
    const float* x    = (const float*)d_in[0];
    const float* qape = (const float*)d_in[1];
    const float* kape = (const float*)d_in[2];
    const float* pos  = (const float*)d_in[3];
    const float* Wq   = (const float*)d_in[4];
    const float* Wk   = (const float*)d_in[5];
    const float* Wv   = (const float*)d_in[6];
    const float* Wp   = (const float*)d_in[7];
    const float* bp   = (const float*)d_in[8];
    float* out = (float*)d_out;

    cudaFuncSetAttribute(qkv_gemm,  cudaFuncAttributeMaxDynamicSharedMemorySize, GEMM_SMEM);
    cudaFuncSetAttribute(proj_gemm, cudaFuncAttributeMaxDynamicSharedMemorySize, GEMM_SMEM);
    cudaFuncSetAttribute(attn_kernel, cudaFuncAttributeMaxDynamicSharedMemorySize, ATTN_SMEM);

    prep_x<<<ML * CD / (256 * 4), 256>>>(x, qape, kape);
    dim3 wgrid(CD * CD / (256 * 4), 4);
    prep_w<<<wgrid, 256>>>(Wq, Wk, Wv, Wp);

    dim3 gemm_grid(CD / 128, ML / 128, 3);
    qkv_gemm<<<gemm_grid, 256, GEMM_SMEM>>>();

    dim3 attn_grid(LS / 64, BATCH * NH);
    attn_kernel<<<attn_grid, 128, ATTN_SMEM>>>(pos);

    dim3 proj_grid(CD / 128, ML / 128, 1);
    proj_gemm<<<proj_grid, 256, GEMM_SMEM>>>(bp, out);
}

// round 17
// speedup vs baseline: 1.3898x; 1.1269x over previous
#include <cuda_runtime.h>
#include <cuda_bf16.h>
#include <cuda_fp16.h>
#include <cstdint>

#define NH 12
#define HD 64
#define CD 768
#define LS 1024
#define BATCH 4
#define ML (BATCH*LS)
#define ATT_SCALE 0.125f
#define LOGMAX 10.0f

// qkv-side scratch: x(+ape) fp16 hi/lo, W single fp16.
__device__ __align__(16) __half g_xqh[ML*CD], g_xql[ML*CD];  // (x+q_ape)*scale
__device__ __align__(16) __half g_xkh[ML*CD], g_xkl[ML*CD];  // x+k_ape
__device__ __align__(16) __half g_xvh[ML*CD], g_xvl[ML*CD];  // x
__device__ __align__(16) __half g_wqf[CD*CD], g_wkf[CD*CD], g_wvf[CD*CD];
// proj-side: bf16 hi/lo (unchanged precision).
__device__ __align__(16) __nv_bfloat16 g_wph[CD*CD], g_wpl[CD*CD];
// Attention-side: Q, K, V all single fp16.
__device__ __align__(16) __half g_qf[ML*CD];                 // [B,H,L,D]
__device__ __align__(16) __half g_kf[ML*CD];
__device__ __align__(16) __half g_vf[ML*CD];
__device__ __align__(16) __nv_bfloat16 g_oh[ML*CD], g_ol[ML*CD];   // [B,L,C]

// ---------------- helpers ----------------
__device__ __forceinline__ uint32_t sptr(const void* p) {
    return (uint32_t)__cvta_generic_to_shared(p);
}
__device__ __forceinline__ void bsplit(float x, float y, uint32_t& hp, uint32_t& lp) {
    __nv_bfloat16 hx = __float2bfloat16_rn(x);
    __nv_bfloat16 hy = __float2bfloat16_rn(y);
    float rx = x - __bfloat162float(hx);
    float ry = y - __bfloat162float(hy);
    __nv_bfloat16 lx = __float2bfloat16_rn(rx);
    __nv_bfloat16 ly = __float2bfloat16_rn(ry);
    hp = (uint32_t)__bfloat16_as_ushort(hx) | ((uint32_t)__bfloat16_as_ushort(hy) << 16);
    lp = (uint32_t)__bfloat16_as_ushort(lx) | ((uint32_t)__bfloat16_as_ushort(ly) << 16);
}
__device__ __forceinline__ void hsplit(float x, float y, uint32_t& hp, uint32_t& lp) {
    __half hx = __float2half_rn(x);
    __half hy = __float2half_rn(y);
    float rx = x - __half2float(hx);
    float ry = y - __half2float(hy);
    __half lx = __float2half_rn(rx);
    __half ly = __float2half_rn(ry);
    hp = (uint32_t)__half_as_ushort(hx) | ((uint32_t)__half_as_ushort(hy) << 16);
    lp = (uint32_t)__half_as_ushort(lx) | ((uint32_t)__half_as_ushort(ly) << 16);
}
__device__ __forceinline__ uint32_t packh2(float lo, float hi) {
    uint32_t r;
    asm("cvt.rn.f16x2.f32 %0, %1, %2;" : "=r"(r) : "f"(hi), "f"(lo));
    return r;
}
__device__ __forceinline__ void ldsm4(uint32_t* r, uint32_t a) {
    asm volatile("ldmatrix.sync.aligned.m8n8.x4.shared.b16 {%0,%1,%2,%3},[%4];\n"
                 : "=r"(r[0]), "=r"(r[1]), "=r"(r[2]), "=r"(r[3]) : "r"(a));
}
__device__ __forceinline__ void ldsm4t(uint32_t* r, uint32_t a) {
    asm volatile("ldmatrix.sync.aligned.m8n8.x4.trans.shared.b16 {%0,%1,%2,%3},[%4];\n"
                 : "=r"(r[0]), "=r"(r[1]), "=r"(r[2]), "=r"(r[3]) : "r"(a));
}
__device__ __forceinline__ void mma_bf16(float* c, const uint32_t* a, uint32_t b0, uint32_t b1) {
    asm volatile(
        "mma.sync.aligned.m16n8k16.row.col.f32.bf16.bf16.f32 "
        "{%0,%1,%2,%3},{%4,%5,%6,%7},{%8,%9},{%0,%1,%2,%3};\n"
        : "+f"(c[0]), "+f"(c[1]), "+f"(c[2]), "+f"(c[3])
        : "r"(a[0]), "r"(a[1]), "r"(a[2]), "r"(a[3]), "r"(b0), "r"(b1));
}
__device__ __forceinline__ void mma_f16(float* c, const uint32_t* a, uint32_t b0, uint32_t b1) {
    asm volatile(
        "mma.sync.aligned.m16n8k16.row.col.f32.f16.f16.f32 "
        "{%0,%1,%2,%3},{%4,%5,%6,%7},{%8,%9},{%0,%1,%2,%3};\n"
        : "+f"(c[0]), "+f"(c[1]), "+f"(c[2]), "+f"(c[3])
        : "r"(a[0]), "r"(a[1]), "r"(a[2]), "r"(a[3]), "r"(b0), "r"(b1));
}
__device__ __forceinline__ void cpa16(uint32_t dst, const void* src) {
    asm volatile("cp.async.cg.shared.global [%0], [%1], 16;\n" :: "r"(dst), "l"(src));
}
__device__ __forceinline__ void cp_commit() { asm volatile("cp.async.commit_group;\n"); }
template<int N> __device__ __forceinline__ void cp_wait() {
    asm volatile("cp.async.wait_group %0;\n" :: "n"(N));
}

// ---------------------------------------------------------------------------
// Prep kernels
// ---------------------------------------------------------------------------
__global__ __launch_bounds__(256) void prep_x(
    const float* __restrict__ x,
    const float* __restrict__ qape,
    const float* __restrict__ kape)
{
    const int idx = (blockIdx.x * 256 + threadIdx.x) * 4;
    const int m = idx / CD;
    const int c = idx - m * CD;
    const int l = m & (LS - 1);

    float4 xv = *(const float4*)(x + idx);
    float4 qa = *(const float4*)(qape + (size_t)l * CD + c);
    float4 ka = *(const float4*)(kape + (size_t)l * CD + c);

    uint32_t h0, l0, h1, l1;
    hsplit((xv.x + qa.x) * ATT_SCALE, (xv.y + qa.y) * ATT_SCALE, h0, l0);
    hsplit((xv.z + qa.z) * ATT_SCALE, (xv.w + qa.w) * ATT_SCALE, h1, l1);
    *(uint2*)(g_xqh + idx) = make_uint2(h0, h1);
    *(uint2*)(g_xql + idx) = make_uint2(l0, l1);

    hsplit(xv.x + ka.x, xv.y + ka.y, h0, l0);
    hsplit(xv.z + ka.z, xv.w + ka.w, h1, l1);
    *(uint2*)(g_xkh + idx) = make_uint2(h0, h1);
    *(uint2*)(g_xkl + idx) = make_uint2(l0, l1);

    hsplit(xv.x, xv.y, h0, l0);
    hsplit(xv.z, xv.w, h1, l1);
    *(uint2*)(g_xvh + idx) = make_uint2(h0, h1);
    *(uint2*)(g_xvl + idx) = make_uint2(l0, l1);
}

__global__ __launch_bounds__(256) void prep_w(
    const float* __restrict__ Wq, const float* __restrict__ Wk,
    const float* __restrict__ Wv, const float* __restrict__ Wp)
{
    const int mat = blockIdx.y;
    const int idx = (blockIdx.x * 256 + threadIdx.x) * 4;
    if (mat < 3) {
        const float* W = (mat == 0) ? Wq : (mat == 1) ? Wk : Wv;
        __half* wf = (mat == 0) ? g_wqf : (mat == 1) ? g_wkf : g_wvf;
        float4 v = *(const float4*)(W + idx);
        *(uint2*)(wf + idx) = make_uint2(packh2(v.x, v.y), packh2(v.z, v.w));
    } else {
        float4 v = *(const float4*)(Wp + idx);
        uint32_t h0, l0, h1, l1;
        bsplit(v.x, v.y, h0, l0);
        bsplit(v.z, v.w, h1, l1);
        *(uint2*)(g_wph + idx) = make_uint2(h0, h1);
        *(uint2*)(g_wpl + idx) = make_uint2(l0, l1);
    }
}

// ---------------------------------------------------------------------------
// QKV GEMM: fp16 split-2 (A hi/lo x W single), 4-stage cp.async ring,
// block 128x128, BK=16, 256 thr, warp 64x32. 32 MMAs per BK-iter.
// ---------------------------------------------------------------------------
#define AST 24
#define GS (128*AST)
#define GIDX(st,row,col) (((st)*128+(row))*AST+(col))
#define QKV_SMEM (3*4*GS*2)          // 3 arrays x 4 stages x fp16 = 73728 B
#define PROJ_SMEM (4*4*GS*2)         // proj keeps 4 arrays = 98304 B

__global__ __launch_bounds__(256, 2) void qkv_gemm()
{
    extern __shared__ __half qsm[];
    __half* Ah = qsm;
    __half* Al = qsm + 4*GS;
    __half* Bw = qsm + 8*GS;

    const int which = blockIdx.z;
    const __half* pAh = (which == 0) ? g_xqh : (which == 1) ? g_xkh : g_xvh;
    const __half* pAl = (which == 0) ? g_xql : (which == 1) ? g_xkl : g_xvl;
    const __half* pBw = (which == 0) ? g_wqf : (which == 1) ? g_wkf : g_wvf;
    __half* outH = (which == 0) ? g_qf : (which == 1) ? g_kf : g_vf;

    const int tid  = threadIdx.x;
    const int lane = tid & 31;
    const int warp = tid >> 5;
    const int gid  = lane >> 2;
    const int tig  = lane & 3;
    const int wm   = warp >> 2;
    const int wn   = warp & 3;

    const int m0 = blockIdx.y * 128;
    const int n0 = blockIdx.x * 128;
    const int lr = tid >> 1;
    const int lc = (tid & 1) << 3;

    const __half* ah = pAh + (size_t)(m0 + lr) * CD + lc;
    const __half* al = pAl + (size_t)(m0 + lr) * CD + lc;
    const __half* bw = pBw + (size_t)(n0 + lr) * CD + lc;

    float c[4][4][4];
#pragma unroll
    for (int i = 0; i < 4; i++)
#pragma unroll
        for (int j = 0; j < 4; j++)
#pragma unroll
            for (int v = 0; v < 4; v++) c[i][j][v] = 0.f;

#pragma unroll
    for (int p = 0; p < 3; p++) {
        const int k0 = p * 16;
        cpa16(sptr(&Ah[GIDX(p, lr, lc)]), ah + k0);
        cpa16(sptr(&Al[GIDX(p, lr, lc)]), al + k0);
        cpa16(sptr(&Bw[GIDX(p, lr, lc)]), bw + k0);
        cp_commit();
    }

    const int arow_s = wm * 64 + (lane & 15);
    const int acol_s = (lane >> 4) * 8;
    const int brow_s = wn * 32 + ((lane >> 4) & 1) * 8 + (lane & 7);
    const int bcol_s = ((lane >> 3) & 1) * 8;

    const int NIT = CD / 16;
    for (int it = 0; it < NIT; ++it) {
        const int st = it & 3;
        if (it < NIT - 2)       cp_wait<2>();
        else if (it == NIT - 2) cp_wait<1>();
        else                    cp_wait<0>();
        __syncthreads();

        if (it + 3 < NIT) {
            const int s2 = (it + 3) & 3;
            const int k0 = (it + 3) * 16;
            cpa16(sptr(&Ah[GIDX(s2, lr, lc)]), ah + k0);
            cpa16(sptr(&Al[GIDX(s2, lr, lc)]), al + k0);
            cpa16(sptr(&Bw[GIDX(s2, lr, lc)]), bw + k0);
            cp_commit();
        }

        uint32_t fah[4][4], fal[4][4], fbw[2][4];
#pragma unroll
        for (int ma = 0; ma < 4; ma++) {
            ldsm4(fah[ma], sptr(&Ah[GIDX(st, arow_s + ma * 16, acol_s)]));
            ldsm4(fal[ma], sptr(&Al[GIDX(st, arow_s + ma * 16, acol_s)]));
        }
#pragma unroll
        for (int np = 0; np < 2; np++)
            ldsm4(fbw[np], sptr(&Bw[GIDX(st, brow_s + np * 16, bcol_s)]));
#pragma unroll
        for (int ma = 0; ma < 4; ma++)
#pragma unroll
            for (int nb = 0; nb < 4; nb++) {
                const int np = nb >> 1, sel = (nb & 1) * 2;
                mma_f16(c[ma][nb], fah[ma], fbw[np][sel], fbw[np][sel + 1]);
                mma_f16(c[ma][nb], fal[ma], fbw[np][sel], fbw[np][sel + 1]);
            }
    }

    // epilogue -> [B,H,L,D]; Q/K/V all single fp16
#pragma unroll
    for (int ma = 0; ma < 4; ma++) {
        int row0 = m0 + wm * 64 + ma * 16 + gid;
        int row1 = row0 + 8;
        int b0i = row0 >> 10, l0 = row0 & (LS - 1);
        int b1i = row1 >> 10, l1 = row1 & (LS - 1);
#pragma unroll
        for (int nb = 0; nb < 4; nb++) {
            int n = n0 + wn * 32 + nb * 8 + 2 * tig;
            int h = n >> 6, d = n & 63;
            size_t o0 = ((size_t)((b0i * NH + h) * LS + l0)) * HD + d;
            size_t o1 = ((size_t)((b1i * NH + h) * LS + l1)) * HD + d;
            *(uint32_t*)(outH + o0) = packh2(c[ma][nb][0], c[ma][nb][1]);
            *(uint32_t*)(outH + o1) = packh2(c[ma][nb][2], c[ma][nb][3]);
        }
    }
}

// ---------------------------------------------------------------------------
// Attention (unchanged from R16): fixed-max softmax, Q persistent smem,
// 2-stage cp.async KV, all-single-fp16 MMAs.
// ---------------------------------------------------------------------------
#define KST 72
#define ATTN_SMEM (18432 + 9216)
#define SIDX(st,arr,row,col) ((((st)*2+(arr))*32+(row))*KST+(col))

__global__ __launch_bounds__(128, 4) void attn_kernel(const float* __restrict__ pos)
{
    extern __shared__ char asmem[];
    __half* Sb = (__half*)asmem;
    __half* Qs = (__half*)(asmem + 18432);

    const int tid  = threadIdx.x;
    const int lane = tid & 31;
    const int warp = tid >> 5;
    const int gid  = lane >> 2;
    const int tig  = lane & 3;

    const int bh = blockIdx.y;
    const int b  = bh / NH;
    const int h  = bh - b * NH;
    const int q0 = blockIdx.x * 64;

    const size_t base = (size_t)bh * LS * HD;

    {
        const int qr = tid >> 1;
        const int qo = (tid & 1) * 32;
        const __half* src = g_qf + base + (size_t)(q0 + qr) * HD + qo;
        uint32_t d0 = sptr(Qs + qr * KST + qo);
#pragma unroll
        for (int cidx = 0; cidx < 4; cidx++) cpa16(d0 + cidx * 16, src + cidx * 8);
    }
    cp_commit();

    const __half* kvsrc = ((warp == 0) ? g_kf : g_vf) + base;

    if (warp < 2) {
        const __half* src = kvsrc + (size_t)lane * HD;
        uint32_t d0 = sptr(&Sb[SIDX(0, warp, lane, 0)]);
#pragma unroll
        for (int cidx = 0; cidx < 8; cidx++) cpa16(d0 + cidx * 16, src + cidx * 8);
    }
    cp_commit();

    const int r = warp * 16 + gid;
    const float* pb0 = pos + ((size_t)(h * LS + q0 + r))     * LS + 2 * tig;
    const float* pb1 = pos + ((size_t)(h * LS + q0 + r + 8)) * LS + 2 * tig;

    const int qrow = warp * 16 + (lane & 15);
    const int qc   = (lane >> 4) * 8;

    float o[8][4];
#pragma unroll
    for (int nd = 0; nd < 8; nd++)
#pragma unroll
        for (int v = 0; v < 4; v++) o[nd][v] = 0.f;
    float li[2] = {0.f, 0.f};

    const int krow_s = ((lane >> 4) & 1) * 8 + (lane & 7);
    const int kcol_s = ((lane >> 3) & 1) * 8;
    const int vrow_s = ((lane >> 3) & 1) * 8 + (lane & 7);
    const int vcol_s = ((lane >> 4) & 1) * 8;

    const int NJ = LS / 32;
    for (int i = 0; i < NJ; i++) {
        const int st = i & 1;
        if (i + 1 < NJ) {
            if (warp < 2) {
                const __half* src = kvsrc + (size_t)((i + 1) * 32 + lane) * HD;
                uint32_t d0 = sptr(&Sb[SIDX(st ^ 1, warp, lane, 0)]);
#pragma unroll
                for (int cidx = 0; cidx < 8; cidx++) cpa16(d0 + cidx * 16, src + cidx * 8);
            }
            cp_commit();
            cp_wait<1>();
        } else {
            cp_wait<0>();
        }
        __syncthreads();

        const int j0 = i * 32;
        float2 pv0[4], pv1[4];
#pragma unroll
        for (int nb = 0; nb < 4; nb++) {
            pv0[nb] = *(const float2*)(pb0 + j0 + nb * 8);
            pv1[nb] = *(const float2*)(pb1 + j0 + nb * 8);
        }

        float s[4][4];
#pragma unroll
        for (int nb = 0; nb < 4; nb++)
#pragma unroll
            for (int v = 0; v < 4; v++) s[nb][v] = 0.f;

#pragma unroll
        for (int kc = 0; kc < 4; kc++) {
            uint32_t qf[4];
            ldsm4(qf, sptr(Qs + qrow * KST + kc * 16 + qc));
#pragma unroll
            for (int np = 0; np < 2; np++) {
                uint32_t kf[4];
                ldsm4(kf, sptr(&Sb[SIDX(st, 0, np * 16 + krow_s, kc * 16 + kcol_s)]));
                mma_f16(s[2*np],   qf, kf[0], kf[1]);
                mma_f16(s[2*np+1], qf, kf[2], kf[3]);
            }
        }

#pragma unroll
        for (int nb = 0; nb < 4; nb++) {
            float e0 = __expf(s[nb][0] + pv0[nb].x - LOGMAX);
            float e1 = __expf(s[nb][1] + pv0[nb].y - LOGMAX);
            float e2 = __expf(s[nb][2] + pv1[nb].x - LOGMAX);
            float e3 = __expf(s[nb][3] + pv1[nb].y - LOGMAX);
            s[nb][0] = e0; s[nb][1] = e1; s[nb][2] = e2; s[nb][3] = e3;
            li[0] += e0 + e1;
            li[1] += e2 + e3;
        }

        uint32_t pf[2][4];
#pragma unroll
        for (int kc = 0; kc < 2; kc++) {
            pf[kc][0] = packh2(s[2*kc][0],   s[2*kc][1]);
            pf[kc][1] = packh2(s[2*kc][2],   s[2*kc][3]);
            pf[kc][2] = packh2(s[2*kc+1][0], s[2*kc+1][1]);
            pf[kc][3] = packh2(s[2*kc+1][2], s[2*kc+1][3]);
        }

#pragma unroll
        for (int kc = 0; kc < 2; kc++)
#pragma unroll
            for (int np = 0; np < 4; np++) {
                uint32_t vf[4];
                ldsm4t(vf, sptr(&Sb[SIDX(st, 1, kc * 16 + vrow_s, np * 16 + vcol_s)]));
                mma_f16(o[2*np],   pf[kc], vf[0], vf[1]);
                mma_f16(o[2*np+1], pf[kc], vf[2], vf[3]);
            }

        __syncthreads();
    }

#pragma unroll
    for (int rp = 0; rp < 2; rp++) {
        li[rp] += __shfl_xor_sync(0xffffffffu, li[rp], 1);
        li[rp] += __shfl_xor_sync(0xffffffffu, li[rp], 2);
    }
    float inv0 = 1.0f / li[0];
    float inv1 = 1.0f / li[1];
#pragma unroll
    for (int nd = 0; nd < 8; nd++) {
        int d = nd * 8 + 2 * tig;
        size_t o0 = ((size_t)(b * LS + q0 + r)) * CD + h * HD + d;
        size_t o1 = ((size_t)(b * LS + q0 + r + 8)) * CD + h * HD + d;
        uint32_t hp, lp;
        bsplit(o[nd][0] * inv0, o[nd][1] * inv0, hp, lp);
        *(uint32_t*)(g_oh + o0) = hp;
        *(uint32_t*)(g_ol + o0) = lp;
        bsplit(o[nd][2] * inv1, o[nd][3] * inv1, hp, lp);
        *(uint32_t*)(g_oh + o1) = hp;
        *(uint32_t*)(g_ol + o1) = lp;
    }
}

// ---------------------------------------------------------------------------
// Output projection: 4-stage ring (bf16 split-3, unchanged).
// ---------------------------------------------------------------------------
__global__ __launch_bounds__(256, 2) void proj_gemm(
    const float* __restrict__ bp,
    float* __restrict__ out)
{
    extern __shared__ __nv_bfloat16 dsm[];
    __nv_bfloat16* Ah = dsm;
    __nv_bfloat16* Al = dsm + 4*GS;
    __nv_bfloat16* Bh = dsm + 8*GS;
    __nv_bfloat16* Bl = dsm + 12*GS;

    const int tid  = threadIdx.x;
    const int lane = tid & 31;
    const int warp = tid >> 5;
    const int gid  = lane >> 2;
    const int tig  = lane & 3;
    const int wm   = warp >> 2;
    const int wn   = warp & 3;

    const int m0 = blockIdx.y * 128;
    const int n0 = blockIdx.x * 128;
    const int lr = tid >> 1;
    const int lc = (tid & 1) << 3;

    const __nv_bfloat16* ah = g_oh  + (size_t)(m0 + lr) * CD + lc;
    const __nv_bfloat16* al = g_ol  + (size_t)(m0 + lr) * CD + lc;
    const __nv_bfloat16* bh = g_wph + (size_t)(n0 + lr) * CD + lc;
    const __nv_bfloat16* bl = g_wpl + (size_t)(n0 + lr) * CD + lc;

    float c[4][4][4];
#pragma unroll
    for (int i = 0; i < 4; i++)
#pragma unroll
        for (int j = 0; j < 4; j++)
#pragma unroll
            for (int v = 0; v < 4; v++) c[i][j][v] = 0.f;

#pragma unroll
    for (int p = 0; p < 3; p++) {
        const int k0 = p * 16;
        cpa16(sptr(&Ah[GIDX(p, lr, lc)]), ah + k0);
        cpa16(sptr(&Al[GIDX(p, lr, lc)]), al + k0);
        cpa16(sptr(&Bh[GIDX(p, lr, lc)]), bh + k0);
        cpa16(sptr(&Bl[GIDX(p, lr, lc)]), bl + k0);
        cp_commit();
    }

    const int arow_s = wm * 64 + (lane & 15);
    const int acol_s = (lane >> 4) * 8;
    const int brow_s = wn * 32 + ((lane >> 4) & 1) * 8 + (lane & 7);
    const int bcol_s = ((lane >> 3) & 1) * 8;

    const int NIT = CD / 16;
    for (int it = 0; it < NIT; ++it) {
        const int st = it & 3;
        if (it < NIT - 2)       cp_wait<2>();
        else if (it == NIT - 2) cp_wait<1>();
        else                    cp_wait<0>();
        __syncthreads();

        if (it + 3 < NIT) {
            const int s2 = (it + 3) & 3;
            const int k0 = (it + 3) * 16;
            cpa16(sptr(&Ah[GIDX(s2, lr, lc)]), ah + k0);
            cpa16(sptr(&Al[GIDX(s2, lr, lc)]), al + k0);
            cpa16(sptr(&Bh[GIDX(s2, lr, lc)]), bh + k0);
            cpa16(sptr(&Bl[GIDX(s2, lr, lc)]), bl + k0);
            cp_commit();
        }

        uint32_t fah[4][4], fal[4][4], fbh[2][4], fbl[2][4];
#pragma unroll
        for (int ma = 0; ma < 4; ma++) {
            ldsm4(fah[ma], sptr(&Ah[GIDX(st, arow_s + ma * 16, acol_s)]));
            ldsm4(fal[ma], sptr(&Al[GIDX(st, arow_s + ma * 16, acol_s)]));
        }
#pragma unroll
        for (int np = 0; np < 2; np++) {
            ldsm4(fbh[np], sptr(&Bh[GIDX(st, brow_s + np * 16, bcol_s)]));
            ldsm4(fbl[np], sptr(&Bl[GIDX(st, brow_s + np * 16, bcol_s)]));
        }
#pragma unroll
        for (int ma = 0; ma < 4; ma++)
#pragma unroll
            for (int nb = 0; nb < 4; nb++) {
                const int np = nb >> 1, sel = (nb & 1) * 2;
                mma_bf16(c[ma][nb], fah[ma], fbh[np][sel], fbh[np][sel + 1]);
                mma_bf16(c[ma][nb], fah[ma], fbl[np][sel], fbl[np][sel + 1]);
                mma_bf16(c[ma][nb], fal[ma], fbh[np][sel], fbh[np][sel + 1]);
            }
    }

#pragma unroll
    for (int ma = 0; ma < 4; ma++) {
        int row0 = m0 + wm * 64 + ma * 16 + gid;
        int row1 = row0 + 8;
#pragma unroll
        for (int nb = 0; nb < 4; nb++) {
            int n = n0 + wn * 32 + nb * 8 + 2 * tig;
            float2 bias = *(const float2*)(bp + n);
            *(float2*)(out + (size_t)row0 * CD + n) =
                make_float2(c[ma][nb][0] + bias.x, c[ma][nb][1] + bias.y);
            *(float2*)(out + (size_t)row1 * CD + n) =
                make_float2(c[ma][nb][2] + bias.x, c[ma][nb][3] + bias.y);
        }
    }
}

// ---------------------------------------------------------------------------
extern "C" void kernel_launch(void* const* d_in, const int* in_sizes, int n_in,
                              void* d_out, int out_size)
{
    const float* x    = (const float*)d_in[0];
    const float* qape = (const float*)d_in[1];
    const float* kape = (const float*)d_in[2];
    const float* pos  = (const float*)d_in[3];
    const float* Wq   = (const float*)d_in[4];
    const float* Wk   = (const float*)d_in[5];
    const float* Wv   = (const float*)d_in[6];
    const float* Wp   = (const float*)d_in[7];
    const float* bp   = (const float*)d_in[8];
    float* out = (float*)d_out;

    cudaFuncSetAttribute(qkv_gemm,  cudaFuncAttributeMaxDynamicSharedMemorySize, QKV_SMEM);
    cudaFuncSetAttribute(proj_gemm, cudaFuncAttributeMaxDynamicSharedMemorySize, PROJ_SMEM);
    cudaFuncSetAttribute(attn_kernel, cudaFuncAttributeMaxDynamicSharedMemorySize, ATTN_SMEM);

    prep_x<<<ML * CD / (256 * 4), 256>>>(x, qape, kape);
    dim3 wgrid(CD * CD / (256 * 4), 4);
    prep_w<<<wgrid, 256>>>(Wq, Wk, Wv, Wp);

    dim3 gemm_grid(CD / 128, ML / 128, 3);
    qkv_gemm<<<gemm_grid, 256, QKV_SMEM>>>();

    dim3 attn_grid(LS / 64, BATCH * NH);
    attn_kernel<<<attn_grid, 128, ATTN_SMEM>>>(pos);

    dim3 proj_grid(CD / 128, ML / 128, 1);
    proj_gemm<<<proj_grid, 256, PROJ_SMEM>>>(bp, out);
}